// round 12
// baseline (speedup 1.0000x reference)
#include <cuda_runtime.h>
#include <cuda_bf16.h>
#include <cstdint>
#include <math.h>

#define N_OBJ 256
#define D_IN  1024
#define C_EMB 256
#define H_DIM 1024
#define O_DIM 1024
#define R_DIM 51
#define NP    (N_OBJ * N_OBJ)   /* 65536 edge rows */
#define BN_EPS 1e-5f
#define SLOPE  0.01f
#define RB_STATS 256
#define N2TOT 1152               /* 1024 feat + 51 rel + 1 conf + 76 pad */

// ---------------- scratch (static device globals; no allocation) ---------------
// RULE (root cause of rounds 2-8): these symbols are ONLY referenced inside
// device code. NEVER passed as kernel arguments from kernel_launch (host code
// would pass the host shadow address; ATS on GB300 makes it read zeros).
__device__ __align__(128) __nv_bfloat16 g_c_hi[(size_t)NP * C_EMB];   // cemb split
__device__ __align__(128) __nv_bfloat16 g_c_lo[(size_t)NP * C_EMB];
__device__ __align__(128) __nv_bfloat16 g_W1t_hi[H_DIM * C_EMB];      // W1c^T split [j][k]
__device__ __align__(128) __nv_bfloat16 g_W1t_lo[H_DIM * C_EMB];
__device__ __align__(128) __nv_bfloat16 g_hb_hi[(size_t)NP * H_DIM];  // h split (pre-BN)
__device__ __align__(128) __nv_bfloat16 g_hb_lo[(size_t)NP * H_DIM];
__device__ __align__(128) __nv_bfloat16 g_W2t_hi[(size_t)N2TOT * H_DIM]; // combined B^T split
__device__ __align__(128) __nv_bfloat16 g_W2t_lo[(size_t)N2TOT * H_DIM];
__device__ float g_hi[N_OBJ * H_DIM];
__device__ float g_hj[N_OBJ * H_DIM];
__device__ float g_part[8 * N_OBJ * H_DIM];   // K-split partials for hi/hj
__device__ float g_ps[RB_STATS * H_DIM];
__device__ float g_pq[RB_STATS * H_DIM];
__device__ float g_scale[H_DIM];
__device__ float g_shift[H_DIM];
__device__ float g_bias2[N2TOT];              // [b2+shift.W2 | rel bias | conf bias | 0]
__device__ float g_wrelc[H_DIM * R_DIM];      // W2 @ W_rel
__device__ float g_wattc[H_DIM];              // W2 @ w_att
__device__ float g_conf[NP];                  // attention logits

__device__ __forceinline__ void mma_bf16(float* c, const uint32_t* a, const uint32_t* b) {
    asm volatile("mma.sync.aligned.m16n8k16.row.col.f32.bf16.bf16.f32 "
                 "{%0,%1,%2,%3}, {%4,%5,%6,%7}, {%8,%9}, {%0,%1,%2,%3};"
                 : "+f"(c[0]), "+f"(c[1]), "+f"(c[2]), "+f"(c[3])
                 : "r"(a[0]), "r"(a[1]), "r"(a[2]), "r"(a[3]), "r"(b[0]), "r"(b[1]));
}
__device__ __forceinline__ void split_bf16(float v, __nv_bfloat16& h, __nv_bfloat16& l) {
    h = __float2bfloat16_rn(v);
    l = __float2bfloat16_rn(v - __bfloat162float(h));
}
__device__ __forceinline__ uint32_t smem_u32(const void* p) {
    uint32_t a;
    asm("{ .reg .u64 t; cvta.to.shared.u64 t, %1; cvt.u32.u64 %0, t; }" : "=r"(a) : "l"(p));
    return a;
}
__device__ __forceinline__ void ldsm_x4(uint32_t* r, uint32_t addr) {
    asm volatile("ldmatrix.sync.aligned.m8n8.x4.shared.b16 {%0,%1,%2,%3}, [%4];"
                 : "=r"(r[0]), "=r"(r[1]), "=r"(r[2]), "=r"(r[3]) : "r"(addr));
}

// ---------------- HMMA bf16x3 GEMM (round-11 structure; ldmatrix fragments) ----
// EPI 1: h = leakyrelu(cemb @ W1c + g_hi[nn]+g_hj[mm]+bias) -> split planes  K=256
// EPI 0: [feat | rel | conf] = h @ Bcomb + g_bias2                           K=1024
#define TK2   16
#define APAD2 24
template<int EPI>
__global__ __launch_bounds__(256)
void mma_gemm(const float* __restrict__ bias,
              float* __restrict__ out_feat,
              float* __restrict__ out_rel)
{
    const __nv_bfloat16* __restrict__ Ahi = (EPI == 1) ? g_c_hi : g_hb_hi;
    const __nv_bfloat16* __restrict__ Alo = (EPI == 1) ? g_c_lo : g_hb_lo;
    const __nv_bfloat16* __restrict__ Bhi = (EPI == 1) ? g_W1t_hi : g_W2t_hi;
    const __nv_bfloat16* __restrict__ Blo = (EPI == 1) ? g_W1t_lo : g_W2t_lo;
    constexpr int K = (EPI == 1) ? C_EMB : H_DIM;
    constexpr int NC = K / TK2;

    __shared__ __align__(16) __nv_bfloat16 sAhi[2][128][APAD2];
    __shared__ __align__(16) __nv_bfloat16 sAlo[2][128][APAD2];
    __shared__ __align__(16) __nv_bfloat16 sBhi[2][128][APAD2];
    __shared__ __align__(16) __nv_bfloat16 sBlo[2][128][APAD2];

    const int tid = threadIdx.x;
    const int lane = tid & 31, wid = tid >> 5;
    const int m0 = blockIdx.y * 128, n0 = blockIdx.x * 128;

    const int m_base = (wid >> 2) * 64;
    const int n_base = (wid & 3) * 32;
    const int fr = lane >> 2;             // fragment row 0..7
    const int fk = (lane & 3) * 2;        // fragment k 0,2,4,6

    const int ld_row = tid >> 1, ld_c = (tid & 1) * 8;

    // ldmatrix per-lane element offsets (validated direct-LDS coords, batched):
    // A x4 tiles: t0=(rowlo,klo)->a0, t1=(rowhi,klo)->a1, t2=(rowlo,khi)->a2, t3=(rowhi,khi)->a3
    const int a_row = m_base + (lane & 15);            // +8 rows via lane bit3
    const int a_col = (lane >> 4) << 3;                // lanes 16-31: k+8
    const uint32_t a_elem = (uint32_t)(a_row * APAD2 + a_col) * 2;
    // B x4 tiles: t0=(n lo,klo)->b[2g][0], t1=(n lo,khi)->b[2g][1], t2=(n hi,klo), t3=(n hi,khi)
    const int b_row = n_base + (lane & 7) + ((lane >> 4) << 3);
    const int b_col = ((lane >> 3) & 1) << 3;
    const uint32_t b_elem = (uint32_t)(b_row * APAD2 + b_col) * 2;

    const uint32_t sb_Ahi = smem_u32(&sAhi[0][0][0]);
    const uint32_t sb_Alo = smem_u32(&sAlo[0][0][0]);
    const uint32_t sb_Bhi = smem_u32(&sBhi[0][0][0]);
    const uint32_t sb_Blo = smem_u32(&sBlo[0][0][0]);
    const uint32_t bufB = 128 * APAD2 * 2;

    float acc[4][4][4];
#pragma unroll
    for (int i = 0; i < 4; i++)
#pragma unroll
        for (int j = 0; j < 4; j++)
#pragma unroll
            for (int r = 0; r < 4; r++) acc[i][j][r] = 0.f;

    // preload chunk 0 into buffer 0
    {
        const size_t ka = (size_t)(m0 + ld_row) * K + ld_c;
        const size_t kb = (size_t)(n0 + ld_row) * K + ld_c;
        *(uint4*)&sAhi[0][ld_row][ld_c] = *(const uint4*)(Ahi + ka);
        *(uint4*)&sAlo[0][ld_row][ld_c] = *(const uint4*)(Alo + ka);
        *(uint4*)&sBhi[0][ld_row][ld_c] = *(const uint4*)(Bhi + kb);
        *(uint4*)&sBlo[0][ld_row][ld_c] = *(const uint4*)(Blo + kb);
    }
    __syncthreads();

    for (int c = 0; c < NC; c++) {
        const int cur = c & 1, nxt = cur ^ 1;
        uint4 pa, pb, pc, pd;
        if (c + 1 < NC) {
            const size_t ka = (size_t)(m0 + ld_row) * K + (c + 1) * TK2 + ld_c;
            const size_t kb = (size_t)(n0 + ld_row) * K + (c + 1) * TK2 + ld_c;
            pa = *(const uint4*)(Ahi + ka);
            pb = *(const uint4*)(Alo + ka);
            pc = *(const uint4*)(Bhi + kb);
            pd = *(const uint4*)(Blo + kb);
        }

        const uint32_t off = cur * bufB;
        uint32_t a_hi[4][4], a_lo[4][4], bh[4], bl[4];
        uint32_t b_hi[4][2], b_lo[4][2];
#pragma unroll
        for (int mt = 0; mt < 4; mt++) {
            const uint32_t adr = a_elem + (uint32_t)(mt * 16 * APAD2) * 2 + off;
            ldsm_x4(a_hi[mt], sb_Ahi + adr);
            ldsm_x4(a_lo[mt], sb_Alo + adr);
        }
#pragma unroll
        for (int ng = 0; ng < 2; ng++) {
            const uint32_t adr = b_elem + (uint32_t)(ng * 16 * APAD2) * 2 + off;
            ldsm_x4(bh, sb_Bhi + adr);
            ldsm_x4(bl, sb_Blo + adr);
            b_hi[ng * 2][0] = bh[0]; b_hi[ng * 2][1] = bh[1];
            b_hi[ng * 2 + 1][0] = bh[2]; b_hi[ng * 2 + 1][1] = bh[3];
            b_lo[ng * 2][0] = bl[0]; b_lo[ng * 2][1] = bl[1];
            b_lo[ng * 2 + 1][0] = bl[2]; b_lo[ng * 2 + 1][1] = bl[3];
        }
#pragma unroll
        for (int mt = 0; mt < 4; mt++)
#pragma unroll
            for (int nt = 0; nt < 4; nt++) {
                mma_bf16(acc[mt][nt], a_hi[mt], b_hi[nt]);
                mma_bf16(acc[mt][nt], a_hi[mt], b_lo[nt]);
                mma_bf16(acc[mt][nt], a_lo[mt], b_hi[nt]);
            }

        if (c + 1 < NC) {
            *(uint4*)&sAhi[nxt][ld_row][ld_c] = pa;
            *(uint4*)&sAlo[nxt][ld_row][ld_c] = pb;
            *(uint4*)&sBhi[nxt][ld_row][ld_c] = pc;
            *(uint4*)&sBlo[nxt][ld_row][ld_c] = pd;
        }
        __syncthreads();
    }

    // epilogue: c0,c1 -> row fr; c2,c3 -> row fr+8
#pragma unroll
    for (int mt = 0; mt < 4; mt++)
#pragma unroll
        for (int nt = 0; nt < 4; nt++) {
            const int col0 = n0 + n_base + nt * 8 + fk;
#pragma unroll
            for (int half = 0; half < 2; half++) {
                const int row = m0 + m_base + mt * 16 + fr + half * 8;
                float v0 = acc[mt][nt][half * 2];
                float v1 = acc[mt][nt][half * 2 + 1];
                if (EPI == 1) {
                    const int nn = row >> 8, mm = row & 255;
                    v0 += g_hi[nn * H_DIM + col0]     + g_hj[mm * H_DIM + col0]     + bias[col0];
                    v1 += g_hi[nn * H_DIM + col0 + 1] + g_hj[mm * H_DIM + col0 + 1] + bias[col0 + 1];
                    v0 = (v0 >= 0.f) ? v0 : SLOPE * v0;
                    v1 = (v1 >= 0.f) ? v1 : SLOPE * v1;
                    __nv_bfloat16 h0, l0, h1, l1;
                    split_bf16(v0, h0, l0);
                    split_bf16(v1, h1, l1);
                    const size_t o = (size_t)row * H_DIM + col0;
                    *(__nv_bfloat162*)(g_hb_hi + o) = __nv_bfloat162(h0, h1);
                    *(__nv_bfloat162*)(g_hb_lo + o) = __nv_bfloat162(l0, l1);
                } else {
                    v0 += g_bias2[col0];
                    v1 += g_bias2[col0 + 1];
                    if (blockIdx.x < 8) {
                        *(float2*)(out_feat + (size_t)row * O_DIM + col0) = make_float2(v0, v1);
                    } else {
                        const int j0 = col0 - 1024;   // even
                        if (j0 < R_DIM)           out_rel[(size_t)row * R_DIM + j0] = v0;
                        if (j0 + 1 < R_DIM)       out_rel[(size_t)row * R_DIM + j0 + 1] = v1;
                        else if (j0 + 1 == R_DIM) g_conf[row] = v1;
                    }
                }
            }
        }
}

// ---------------- hi/hj: K-split fp32 GEMM (128 blocks) + reduce ---------------
__launch_bounds__(256)
__global__ void gemm_hij(const float* __restrict__ feats, const float* __restrict__ W1)
{
    const int which = blockIdx.z >> 2;
    const int kc = blockIdx.z & 3;
    __shared__ float As[8][132];
    __shared__ float Bs[8][128];
    const int tid = threadIdx.x;
    const int tx = tid & 15, ty = tid >> 4;
    const int m0 = blockIdx.y * 128, n0 = blockIdx.x * 128;
    float acc[8][8];
#pragma unroll
    for (int i = 0; i < 8; i++)
#pragma unroll
        for (int j = 0; j < 8; j++) acc[i][j] = 0.f;
    const int ar = tid >> 1, ak = (tid & 1) * 4;
    const int bk = tid >> 5, bc = (tid & 31) * 4;
    const float* Aptr = feats + (size_t)(m0 + ar) * 1024 + kc * 256 + ak;
    const float* Bptr = W1 + (size_t)(which * D_IN + kc * 256 + bk) * 1024 + n0 + bc;
    for (int k0 = 0; k0 < 256; k0 += 8) {
        float4 av = *(const float4*)(Aptr + k0);
        float4 bv = *(const float4*)(Bptr + (size_t)k0 * 1024);
        As[ak][ar] = av.x; As[ak + 1][ar] = av.y; As[ak + 2][ar] = av.z; As[ak + 3][ar] = av.w;
        *(float4*)(&Bs[bk][bc]) = bv;
        __syncthreads();
#pragma unroll
        for (int kk = 0; kk < 8; kk++) {
            float a[8], b[8];
#pragma unroll
            for (int i = 0; i < 8; i++) a[i] = As[kk][ty * 8 + i];
#pragma unroll
            for (int j = 0; j < 8; j++) b[j] = Bs[kk][tx * 8 + j];
#pragma unroll
            for (int i = 0; i < 8; i++)
#pragma unroll
                for (int j = 0; j < 8; j++) acc[i][j] += a[i] * b[j];
        }
        __syncthreads();
    }
    float* dst = g_part + (size_t)blockIdx.z * N_OBJ * H_DIM;
#pragma unroll
    for (int i = 0; i < 8; i++)
#pragma unroll
        for (int j = 0; j < 8; j++)
            dst[(size_t)(m0 + ty * 8 + i) * 1024 + n0 + tx * 8 + j] = acc[i][j];
}

__global__ void reduce_hij()
{
    const int idx = blockIdx.x * 256 + threadIdx.x;
    const int which = idx >> 18;
    const int base = idx & (N_OBJ * H_DIM - 1);
    const size_t stride = (size_t)N_OBJ * H_DIM;
    const float* p = g_part + (size_t)which * 4 * stride + base;
    const float s = p[0] + p[stride] + p[2 * stride] + p[3 * stride];
    if (which == 0) g_hi[base] = s;
    else            g_hj[base] = s;
}

// ---------------- converters ---------------------------------------------------
__global__ void convert_cemb(const float* __restrict__ in)
{
    const size_t i = ((size_t)blockIdx.x * 256 + threadIdx.x) * 4;
    if (i >= (size_t)NP * C_EMB) return;
    const float4 v4 = *(const float4*)(in + i);
    const float v[4] = { v4.x, v4.y, v4.z, v4.w };
    uint32_t hw[2], lw[2];
#pragma unroll
    for (int p = 0; p < 2; p++) {
        __nv_bfloat16 h0, l0, h1, l1;
        split_bf16(v[2 * p], h0, l0);
        split_bf16(v[2 * p + 1], h1, l1);
        hw[p] = (uint32_t)__bfloat16_as_ushort(h0) | ((uint32_t)__bfloat16_as_ushort(h1) << 16);
        lw[p] = (uint32_t)__bfloat16_as_ushort(l0) | ((uint32_t)__bfloat16_as_ushort(l1) << 16);
    }
    *(uint2*)((char*)g_c_hi + i * 2) = make_uint2(hw[0], hw[1]);
    *(uint2*)((char*)g_c_lo + i * 2) = make_uint2(lw[0], lw[1]);
}

// W1c^T split via 32x32 tiled transpose. grid (C_EMB/32, H_DIM/32), 256 thr.
__global__ void split_W1t(const float* __restrict__ W1)
{
    __shared__ float t[32][33];
    const int kb = blockIdx.x * 32;
    const int jb = blockIdx.y * 32;
    const int tx = threadIdx.x & 31, ty = threadIdx.x >> 5;
#pragma unroll
    for (int r = 0; r < 4; r++) {
        const int k = kb + ty + r * 8;
        t[ty + r * 8][tx] = W1[(size_t)(2 * D_IN + k) * H_DIM + jb + tx];
    }
    __syncthreads();
#pragma unroll
    for (int r = 0; r < 4; r++) {
        const int j = jb + ty + r * 8;
        const int k = kb + tx;
        __nv_bfloat16 h, l;
        split_bf16(t[tx][ty + r * 8], h, l);
        g_W1t_hi[(size_t)j * C_EMB + k] = h;
        g_W1t_lo[(size_t)j * C_EMB + k] = l;
    }
}

// wrelc = W2 @ W_rel [1024,51], wattc = W2 @ w_att [1024]  (one block per k-row)
__global__ void small_mats(const float* __restrict__ W2, const float* __restrict__ Wrel,
                           const float* __restrict__ watt)
{
    __shared__ float row[1024];
    const int i = blockIdx.x, tid = threadIdx.x;
    for (int o = tid; o < 1024; o += 256) row[o] = W2[(size_t)i * O_DIM + o];
    __syncthreads();
    if (tid < R_DIM) {
        float s = 0.f;
        for (int o = 0; o < 1024; o++) s += row[o] * Wrel[(size_t)o * R_DIM + tid];
        g_wrelc[i * R_DIM + tid] = s;
    } else if (tid == R_DIM) {
        float s = 0.f;
        for (int o = 0; o < 1024; o++) s += row[o] * watt[o];
        g_wattc[i] = s;
    }
}

// (scale.W2)^T split via 32x32 tiled transpose (cols 0..1023)
__global__ void build_W2ts(const float* __restrict__ W2)
{
    __shared__ float t[32][33];
    const int kb = blockIdx.x * 32;
    const int jb = blockIdx.y * 32;
    const int tx = threadIdx.x & 31, ty = threadIdx.x >> 5;
#pragma unroll
    for (int r = 0; r < 4; r++) {
        const int k = kb + ty + r * 8;
        t[ty + r * 8][tx] = W2[(size_t)k * O_DIM + jb + tx];
    }
    __syncthreads();
#pragma unroll
    for (int r = 0; r < 4; r++) {
        const int j = jb + ty + r * 8;
        const int k = kb + tx;
        __nv_bfloat16 h, l;
        split_bf16(g_scale[k] * t[tx][ty + r * 8], h, l);
        g_W2t_hi[(size_t)j * H_DIM + k] = h;
        g_W2t_lo[(size_t)j * H_DIM + k] = l;
    }
}

// extra B^T columns 1024..1151: rel (scale.wrelc), conf (scale.wattc), zero pad
__global__ void build_Bextra()
{
    const int j = 1024 + blockIdx.x;
    const int k = blockIdx.y * 256 + threadIdx.x;
    const int j0 = j - 1024;
    float w = 0.f;
    if (j0 < R_DIM)       w = g_scale[k] * g_wrelc[k * R_DIM + j0];
    else if (j0 == R_DIM) w = g_scale[k] * g_wattc[k];
    __nv_bfloat16 h, l;
    split_bf16(w, h, l);
    g_W2t_hi[(size_t)j * H_DIM + k] = h;
    g_W2t_lo[(size_t)j * H_DIM + k] = l;
}

// bias2[j<1024] = b2[j] + sum_k shift[k] * W2[k][j]
__global__ void build_bias2(const float* __restrict__ W2, const float* __restrict__ b2)
{
    const int j = blockIdx.x * 256 + threadIdx.x;
    float s = b2[j];
#pragma unroll 4
    for (int k = 0; k < H_DIM; k++)
        s += g_shift[k] * W2[(size_t)k * O_DIM + j];
    g_bias2[j] = s;
}

// bias2[1024+j0]: rel -> bias2[:1024]@Wrel + brel ; conf -> bias2.watt + batt ; 0 pad
__global__ void build_biasX(const float* __restrict__ Wrel, const float* __restrict__ brel,
                            const float* __restrict__ watt, const float* __restrict__ batt)
{
    __shared__ float red[256];
    const int j0 = blockIdx.x, tid = threadIdx.x;
    float a = 0.f;
    if (j0 < R_DIM) {
        for (int o = tid; o < 1024; o += 256) a += g_bias2[o] * Wrel[(size_t)o * R_DIM + j0];
    } else if (j0 == R_DIM) {
        for (int o = tid; o < 1024; o += 256) a += g_bias2[o] * watt[o];
    }
    red[tid] = a;
    __syncthreads();
    for (int o = 128; o; o >>= 1) {
        if (tid < o) red[tid] += red[tid + o];
        __syncthreads();
    }
    if (tid == 0) {
        float b = 0.f;
        if (j0 < R_DIM)       b = red[0] + brel[j0];
        else if (j0 == R_DIM) b = red[0] + batt[0];
        g_bias2[1024 + j0] = b;
    }
}

// ---------------- BN stats from split planes (deterministic) -------------------
__global__ void stats_planes()
{
    const int cp = blockIdx.x * 256 + threadIdx.x;
    const int rb = blockIdx.y;
    const int c0 = cp * 2;
    float s0 = 0.f, s1 = 0.f, q0 = 0.f, q1 = 0.f;
#pragma unroll 4
    for (int r = 0; r < 256; r++) {
        const size_t o = (size_t)(rb * 256 + r) * H_DIM + c0;
        const __nv_bfloat162 h2 = *(const __nv_bfloat162*)(g_hb_hi + o);
        const __nv_bfloat162 l2 = *(const __nv_bfloat162*)(g_hb_lo + o);
        const float v0 = __bfloat162float(h2.x) + __bfloat162float(l2.x);
        const float v1 = __bfloat162float(h2.y) + __bfloat162float(l2.y);
        s0 += v0; q0 += v0 * v0;
        s1 += v1; q1 += v1 * v1;
    }
    g_ps[rb * H_DIM + c0] = s0; g_ps[rb * H_DIM + c0 + 1] = s1;
    g_pq[rb * H_DIM + c0] = q0; g_pq[rb * H_DIM + c0 + 1] = q1;
}

__global__ void finalize_bn(const float* __restrict__ gamma, const float* __restrict__ beta)
{
    const int c = blockIdx.x * 256 + threadIdx.x;
    float s = 0.f, q = 0.f;
#pragma unroll
    for (int i = 0; i < RB_STATS; i++) { s += g_ps[i * H_DIM + c]; q += g_pq[i * H_DIM + c]; }
    const float inv = 1.0f / (float)NP;
    const float mean = s * inv;
    const float var = q * inv - mean * mean;
    const float sc = gamma[c] * rsqrtf(var + BN_EPS);
    g_scale[c] = sc;
    g_shift[c] = beta[c] - mean * sc;
}

// ---------------- softmax + weighted aggregation -------------------------------
__global__ void attn_agg(const float* __restrict__ feat, float* __restrict__ enhanced)
{
    __shared__ float conf[N_OBJ];
    __shared__ float red[256];
    const int n = blockIdx.x, tid = threadIdx.x;
    const int c0 = blockIdx.y * 256;
    const float v = g_conf[n * N_OBJ + tid];
    red[tid] = v;
    __syncthreads();
    for (int o = 128; o; o >>= 1) {
        if (tid < o) red[tid] = fmaxf(red[tid], red[tid + o]);
        __syncthreads();
    }
    const float mx = red[0];
    __syncthreads();
    const float e = expf(v - mx);
    red[tid] = e;
    __syncthreads();
    for (int o = 128; o; o >>= 1) {
        if (tid < o) red[tid] += red[tid + o];
        __syncthreads();
    }
    const float p = e / red[0];
    __syncthreads();
    conf[tid] = p;
    __syncthreads();

    float acc = 0.f;
    const float* base = feat + (size_t)n * N_OBJ * O_DIM + c0 + tid;
#pragma unroll 4
    for (int m = 0; m < N_OBJ; m++)
        acc += conf[m] * base[(size_t)m * O_DIM];
    enhanced[(size_t)n * O_DIM + c0 + tid] = acc;
}

// ---------------- launcher ------------------------------------------------------
// NOTE: every kernel argument below is a d_in/d_out pointer. Device scratch is
// reached only through device-code symbol references.
extern "C" void kernel_launch(void* const* d_in, const int* in_sizes, int n_in,
                              void* d_out, int out_size)
{
    const float* feats = (const float*)d_in[0];
    const float* cemb  = (const float*)d_in[1];
    const float* W1    = (const float*)d_in[2];
    const float* b1    = (const float*)d_in[3];
    const float* gamma = (const float*)d_in[4];
    const float* beta  = (const float*)d_in[5];
    const float* W2    = (const float*)d_in[6];
    const float* b2    = (const float*)d_in[7];
    const float* watt  = (const float*)d_in[8];
    const float* batt  = (const float*)d_in[9];
    const float* Wrel  = (const float*)d_in[10];
    const float* brel  = (const float*)d_in[11];

    float* out      = (float*)d_out;
    float* feat     = out;
    float* enhanced = out + (size_t)NP * O_DIM;
    float* relation = enhanced + (size_t)N_OBJ * O_DIM;

    // converters + small mats (independent of GEMMs)
    convert_cemb<<<(int)(((size_t)NP * C_EMB / 4 + 255) / 256), 256>>>(cemb);
    split_W1t<<<dim3(C_EMB / 32, H_DIM / 32), 256>>>(W1);
    small_mats<<<H_DIM, 256>>>(W2, Wrel, watt);

    // hi/hj: K-split GEMM + deterministic reduce
    gemm_hij<<<dim3(8, 2, 8), 256>>>(feats, W1);
    reduce_hij<<<2 * N_OBJ * H_DIM / 256, 256>>>();

    // GEMM1 (HMMA): h = leakyrelu(cemb @ W1c + hi + hj + b1) -> split planes
    mma_gemm<1><<<dim3(8, 512), 256>>>(b1, nullptr, nullptr);

    // BN stats + fold into combined B / bias
    stats_planes<<<dim3(2, RB_STATS), 256>>>();
    finalize_bn<<<4, 256>>>(gamma, beta);
    build_W2ts<<<dim3(H_DIM / 32, O_DIM / 32), 256>>>(W2);
    build_Bextra<<<dim3(128, 4), 256>>>();
    build_bias2<<<O_DIM / 256, 256>>>(W2, b2);
    build_biasX<<<128, 256>>>(Wrel, brel, watt, batt);

    // GEMM2 (HMMA): [feat | relation | conf] = h @ Bcomb + bias2
    mma_gemm<0><<<dim3(9, 512), 256>>>(nullptr, feat, relation);

    // attention softmax + aggregation (logits from GEMM2)
    attn_agg<<<dim3(N_OBJ, 4), 256>>>(feat, enhanced);
}

// round 13
// speedup vs baseline: 1.0566x; 1.0566x over previous
#include <cuda_runtime.h>
#include <cuda_bf16.h>
#include <cstdint>
#include <math.h>

#define N_OBJ 256
#define D_IN  1024
#define C_EMB 256
#define H_DIM 1024
#define O_DIM 1024
#define R_DIM 51
#define NP    (N_OBJ * N_OBJ)   /* 65536 edge rows */
#define BN_EPS 1e-5f
#define SLOPE  0.01f
#define RB_STATS 256
#define N2TOT 1152               /* 1024 feat + 51 rel + 1 conf + 76 pad */

// ---------------- scratch (static device globals; no allocation) ---------------
// RULE (root cause of rounds 2-8): these symbols are ONLY referenced inside
// device code. NEVER passed as kernel arguments from kernel_launch (host code
// would pass the host shadow address; ATS on GB300 makes it read zeros).
__device__ __align__(128) __nv_bfloat16 g_c_hi[(size_t)NP * C_EMB];   // cemb split
__device__ __align__(128) __nv_bfloat16 g_c_lo[(size_t)NP * C_EMB];
__device__ __align__(128) __nv_bfloat16 g_W1t_hi[H_DIM * C_EMB];      // W1c^T split [j][k]
__device__ __align__(128) __nv_bfloat16 g_W1t_lo[H_DIM * C_EMB];
__device__ __align__(128) __nv_bfloat16 g_hb_hi[(size_t)NP * H_DIM];  // h split (pre-BN)
__device__ __align__(128) __nv_bfloat16 g_hb_lo[(size_t)NP * H_DIM];
__device__ __align__(128) __nv_bfloat16 g_W2t_hi[(size_t)N2TOT * H_DIM]; // combined B^T split
__device__ __align__(128) __nv_bfloat16 g_W2t_lo[(size_t)N2TOT * H_DIM];
__device__ float g_hi[N_OBJ * H_DIM];
__device__ float g_hj[N_OBJ * H_DIM];
__device__ float g_part[8 * N_OBJ * H_DIM];   // K-split partials for hi/hj
__device__ float g_ps[RB_STATS * H_DIM];
__device__ float g_pq[RB_STATS * H_DIM];
__device__ float g_scale[H_DIM];
__device__ float g_shift[H_DIM];
__device__ float g_bias2[N2TOT];              // [b2+shift.W2 | rel bias | conf bias | 0]
__device__ float g_wrelc[H_DIM * R_DIM];      // W2 @ W_rel
__device__ float g_wattc[H_DIM];              // W2 @ w_att
__device__ float g_conf[NP];                  // attention logits

__device__ __forceinline__ void mma_bf16(float* c, const uint32_t* a, const uint32_t* b) {
    asm volatile("mma.sync.aligned.m16n8k16.row.col.f32.bf16.bf16.f32 "
                 "{%0,%1,%2,%3}, {%4,%5,%6,%7}, {%8,%9}, {%0,%1,%2,%3};"
                 : "+f"(c[0]), "+f"(c[1]), "+f"(c[2]), "+f"(c[3])
                 : "r"(a[0]), "r"(a[1]), "r"(a[2]), "r"(a[3]), "r"(b[0]), "r"(b[1]));
}
__device__ __forceinline__ void split_bf16(float v, __nv_bfloat16& h, __nv_bfloat16& l) {
    h = __float2bfloat16_rn(v);
    l = __float2bfloat16_rn(v - __bfloat162float(h));
}
__device__ __forceinline__ uint32_t smem_u32(const void* p) {
    uint32_t a;
    asm("{ .reg .u64 t; cvta.to.shared.u64 t, %1; cvt.u32.u64 %0, t; }" : "=r"(a) : "l"(p));
    return a;
}
__device__ __forceinline__ void cp16(uint32_t s, const void* g) {
    asm volatile("cp.async.cg.shared.global [%0], [%1], 16;" :: "r"(s), "l"(g));
}
#define CP_COMMIT() asm volatile("cp.async.commit_group;" ::: "memory")
#define CP_WAIT0()  asm volatile("cp.async.wait_group 0;" ::: "memory")

// ---------------- HMMA bf16x3 GEMM (round-11 fragments; cp.async staging) ------
// EPI 1: h = leakyrelu(cemb @ W1c + g_hi[nn]+g_hj[mm]+bias) -> split planes  K=256
// EPI 0: [feat | rel | conf] = h @ Bcomb + g_bias2                           K=1024
// Drain discipline: wait_group 0 runs BEFORE issuing the next chunk, so exactly
// one group (the chunk about to be consumed) is pending at each wait.
#define TK2   16
#define APAD2 24
template<int EPI>
__global__ __launch_bounds__(256)
void mma_gemm(const float* __restrict__ bias,
              float* __restrict__ out_feat,
              float* __restrict__ out_rel)
{
    const __nv_bfloat16* __restrict__ Ahi = (EPI == 1) ? g_c_hi : g_hb_hi;
    const __nv_bfloat16* __restrict__ Alo = (EPI == 1) ? g_c_lo : g_hb_lo;
    const __nv_bfloat16* __restrict__ Bhi = (EPI == 1) ? g_W1t_hi : g_W2t_hi;
    const __nv_bfloat16* __restrict__ Blo = (EPI == 1) ? g_W1t_lo : g_W2t_lo;
    constexpr int K = (EPI == 1) ? C_EMB : H_DIM;
    constexpr int NC = K / TK2;

    __shared__ __align__(16) __nv_bfloat16 sAhi[2][128][APAD2];
    __shared__ __align__(16) __nv_bfloat16 sAlo[2][128][APAD2];
    __shared__ __align__(16) __nv_bfloat16 sBhi[2][128][APAD2];
    __shared__ __align__(16) __nv_bfloat16 sBlo[2][128][APAD2];

    const int tid = threadIdx.x;
    const int lane = tid & 31, wid = tid >> 5;
    const int m0 = blockIdx.y * 128, n0 = blockIdx.x * 128;

    const int m_base = (wid >> 2) * 64;
    const int n_base = (wid & 3) * 32;
    const int fr = lane >> 2;             // fragment row 0..7
    const int fk = (lane & 3) * 2;        // fragment k 0,2,4,6

    const int ld_row = tid >> 1, ld_c = (tid & 1) * 8;

    // cp.async loader: one 16B granule per plane per thread per chunk
    auto load_chunk = [&](int c, int s) {
        const size_t ka = (size_t)(m0 + ld_row) * K + c * TK2 + ld_c;
        const size_t kb = (size_t)(n0 + ld_row) * K + c * TK2 + ld_c;
        cp16(smem_u32(&sAhi[s][ld_row][ld_c]), Ahi + ka);
        cp16(smem_u32(&sAlo[s][ld_row][ld_c]), Alo + ka);
        cp16(smem_u32(&sBhi[s][ld_row][ld_c]), Bhi + kb);
        cp16(smem_u32(&sBlo[s][ld_row][ld_c]), Blo + kb);
    };

    float acc[4][4][4];
#pragma unroll
    for (int i = 0; i < 4; i++)
#pragma unroll
        for (int j = 0; j < 4; j++)
#pragma unroll
            for (int r = 0; r < 4; r++) acc[i][j][r] = 0.f;

    load_chunk(0, 0);
    CP_COMMIT();

    for (int c = 0; c < NC; c++) {
        const int cur = c & 1, nxt = cur ^ 1;
        CP_WAIT0();          // drain chunk c (sole pending group)
        __syncthreads();     // all threads see buffer cur; nxt free to overwrite
        if (c + 1 < NC) load_chunk(c + 1, nxt);
        CP_COMMIT();         // overlaps with compute below

        uint32_t a_hi[4][4], a_lo[4][4], b_hi[4][2], b_lo[4][2];
#pragma unroll
        for (int mt = 0; mt < 4; mt++) {
            const int r0 = m_base + mt * 16 + fr;
            a_hi[mt][0] = *(const uint32_t*)&sAhi[cur][r0    ][fk];
            a_hi[mt][1] = *(const uint32_t*)&sAhi[cur][r0 + 8][fk];
            a_hi[mt][2] = *(const uint32_t*)&sAhi[cur][r0    ][fk + 8];
            a_hi[mt][3] = *(const uint32_t*)&sAhi[cur][r0 + 8][fk + 8];
            a_lo[mt][0] = *(const uint32_t*)&sAlo[cur][r0    ][fk];
            a_lo[mt][1] = *(const uint32_t*)&sAlo[cur][r0 + 8][fk];
            a_lo[mt][2] = *(const uint32_t*)&sAlo[cur][r0    ][fk + 8];
            a_lo[mt][3] = *(const uint32_t*)&sAlo[cur][r0 + 8][fk + 8];
        }
#pragma unroll
        for (int nt = 0; nt < 4; nt++) {
            const int n = n_base + nt * 8 + fr;
            b_hi[nt][0] = *(const uint32_t*)&sBhi[cur][n][fk];
            b_hi[nt][1] = *(const uint32_t*)&sBhi[cur][n][fk + 8];
            b_lo[nt][0] = *(const uint32_t*)&sBlo[cur][n][fk];
            b_lo[nt][1] = *(const uint32_t*)&sBlo[cur][n][fk + 8];
        }
#pragma unroll
        for (int mt = 0; mt < 4; mt++)
#pragma unroll
            for (int nt = 0; nt < 4; nt++) {
                mma_bf16(acc[mt][nt], a_hi[mt], b_hi[nt]);
                mma_bf16(acc[mt][nt], a_hi[mt], b_lo[nt]);
                mma_bf16(acc[mt][nt], a_lo[mt], b_hi[nt]);
            }
        __syncthreads();     // done reading cur before it is refilled at c+2
    }

    // epilogue: c0,c1 -> row fr; c2,c3 -> row fr+8
#pragma unroll
    for (int mt = 0; mt < 4; mt++)
#pragma unroll
        for (int nt = 0; nt < 4; nt++) {
            const int col0 = n0 + n_base + nt * 8 + fk;
#pragma unroll
            for (int half = 0; half < 2; half++) {
                const int row = m0 + m_base + mt * 16 + fr + half * 8;
                float v0 = acc[mt][nt][half * 2];
                float v1 = acc[mt][nt][half * 2 + 1];
                if (EPI == 1) {
                    const int nn = row >> 8, mm = row & 255;
                    v0 += g_hi[nn * H_DIM + col0]     + g_hj[mm * H_DIM + col0]     + bias[col0];
                    v1 += g_hi[nn * H_DIM + col0 + 1] + g_hj[mm * H_DIM + col0 + 1] + bias[col0 + 1];
                    v0 = (v0 >= 0.f) ? v0 : SLOPE * v0;
                    v1 = (v1 >= 0.f) ? v1 : SLOPE * v1;
                    __nv_bfloat16 h0, l0, h1, l1;
                    split_bf16(v0, h0, l0);
                    split_bf16(v1, h1, l1);
                    const size_t o = (size_t)row * H_DIM + col0;
                    *(__nv_bfloat162*)(g_hb_hi + o) = __nv_bfloat162(h0, h1);
                    *(__nv_bfloat162*)(g_hb_lo + o) = __nv_bfloat162(l0, l1);
                } else {
                    v0 += g_bias2[col0];
                    v1 += g_bias2[col0 + 1];
                    if (blockIdx.x < 8) {
                        *(float2*)(out_feat + (size_t)row * O_DIM + col0) = make_float2(v0, v1);
                    } else {
                        const int j0 = col0 - 1024;   // even
                        if (j0 < R_DIM)           out_rel[(size_t)row * R_DIM + j0] = v0;
                        if (j0 + 1 < R_DIM)       out_rel[(size_t)row * R_DIM + j0 + 1] = v1;
                        else if (j0 + 1 == R_DIM) g_conf[row] = v1;
                    }
                }
            }
        }
}

// ---------------- hi/hj: K-split fp32 GEMM (128 blocks) + reduce ---------------
__launch_bounds__(256)
__global__ void gemm_hij(const float* __restrict__ feats, const float* __restrict__ W1)
{
    const int which = blockIdx.z >> 2;
    const int kc = blockIdx.z & 3;
    __shared__ float As[8][132];
    __shared__ float Bs[8][128];
    const int tid = threadIdx.x;
    const int tx = tid & 15, ty = tid >> 4;
    const int m0 = blockIdx.y * 128, n0 = blockIdx.x * 128;
    float acc[8][8];
#pragma unroll
    for (int i = 0; i < 8; i++)
#pragma unroll
        for (int j = 0; j < 8; j++) acc[i][j] = 0.f;
    const int ar = tid >> 1, ak = (tid & 1) * 4;
    const int bk = tid >> 5, bc = (tid & 31) * 4;
    const float* Aptr = feats + (size_t)(m0 + ar) * 1024 + kc * 256 + ak;
    const float* Bptr = W1 + (size_t)(which * D_IN + kc * 256 + bk) * 1024 + n0 + bc;
    for (int k0 = 0; k0 < 256; k0 += 8) {
        float4 av = *(const float4*)(Aptr + k0);
        float4 bv = *(const float4*)(Bptr + (size_t)k0 * 1024);
        As[ak][ar] = av.x; As[ak + 1][ar] = av.y; As[ak + 2][ar] = av.z; As[ak + 3][ar] = av.w;
        *(float4*)(&Bs[bk][bc]) = bv;
        __syncthreads();
#pragma unroll
        for (int kk = 0; kk < 8; kk++) {
            float a[8], b[8];
#pragma unroll
            for (int i = 0; i < 8; i++) a[i] = As[kk][ty * 8 + i];
#pragma unroll
            for (int j = 0; j < 8; j++) b[j] = Bs[kk][tx * 8 + j];
#pragma unroll
            for (int i = 0; i < 8; i++)
#pragma unroll
                for (int j = 0; j < 8; j++) acc[i][j] += a[i] * b[j];
        }
        __syncthreads();
    }
    float* dst = g_part + (size_t)blockIdx.z * N_OBJ * H_DIM;
#pragma unroll
    for (int i = 0; i < 8; i++)
#pragma unroll
        for (int j = 0; j < 8; j++)
            dst[(size_t)(m0 + ty * 8 + i) * 1024 + n0 + tx * 8 + j] = acc[i][j];
}

__global__ void reduce_hij()
{
    const int idx = blockIdx.x * 256 + threadIdx.x;
    const int which = idx >> 18;
    const int base = idx & (N_OBJ * H_DIM - 1);
    const size_t stride = (size_t)N_OBJ * H_DIM;
    const float* p = g_part + (size_t)which * 4 * stride + base;
    const float s = p[0] + p[stride] + p[2 * stride] + p[3 * stride];
    if (which == 0) g_hi[base] = s;
    else            g_hj[base] = s;
}

// ---------------- converters ---------------------------------------------------
__global__ void convert_cemb(const float* __restrict__ in)
{
    const size_t i = ((size_t)blockIdx.x * 256 + threadIdx.x) * 4;
    if (i >= (size_t)NP * C_EMB) return;
    const float4 v4 = *(const float4*)(in + i);
    const float v[4] = { v4.x, v4.y, v4.z, v4.w };
    uint32_t hw[2], lw[2];
#pragma unroll
    for (int p = 0; p < 2; p++) {
        __nv_bfloat16 h0, l0, h1, l1;
        split_bf16(v[2 * p], h0, l0);
        split_bf16(v[2 * p + 1], h1, l1);
        hw[p] = (uint32_t)__bfloat16_as_ushort(h0) | ((uint32_t)__bfloat16_as_ushort(h1) << 16);
        lw[p] = (uint32_t)__bfloat16_as_ushort(l0) | ((uint32_t)__bfloat16_as_ushort(l1) << 16);
    }
    *(uint2*)((char*)g_c_hi + i * 2) = make_uint2(hw[0], hw[1]);
    *(uint2*)((char*)g_c_lo + i * 2) = make_uint2(lw[0], lw[1]);
}

// W1c^T split via 32x32 tiled transpose. grid (C_EMB/32, H_DIM/32), 256 thr.
__global__ void split_W1t(const float* __restrict__ W1)
{
    __shared__ float t[32][33];
    const int kb = blockIdx.x * 32;
    const int jb = blockIdx.y * 32;
    const int tx = threadIdx.x & 31, ty = threadIdx.x >> 5;
#pragma unroll
    for (int r = 0; r < 4; r++) {
        const int k = kb + ty + r * 8;
        t[ty + r * 8][tx] = W1[(size_t)(2 * D_IN + k) * H_DIM + jb + tx];
    }
    __syncthreads();
#pragma unroll
    for (int r = 0; r < 4; r++) {
        const int j = jb + ty + r * 8;
        const int k = kb + tx;
        __nv_bfloat16 h, l;
        split_bf16(t[tx][ty + r * 8], h, l);
        g_W1t_hi[(size_t)j * C_EMB + k] = h;
        g_W1t_lo[(size_t)j * C_EMB + k] = l;
    }
}

// wrelc = W2 @ W_rel [1024,51], wattc = W2 @ w_att [1024]  (one block per k-row)
__global__ void small_mats(const float* __restrict__ W2, const float* __restrict__ Wrel,
                           const float* __restrict__ watt)
{
    __shared__ float row[1024];
    const int i = blockIdx.x, tid = threadIdx.x;
    for (int o = tid; o < 1024; o += 256) row[o] = W2[(size_t)i * O_DIM + o];
    __syncthreads();
    if (tid < R_DIM) {
        float s = 0.f;
        for (int o = 0; o < 1024; o++) s += row[o] * Wrel[(size_t)o * R_DIM + tid];
        g_wrelc[i * R_DIM + tid] = s;
    } else if (tid == R_DIM) {
        float s = 0.f;
        for (int o = 0; o < 1024; o++) s += row[o] * watt[o];
        g_wattc[i] = s;
    }
}

// (scale.W2)^T split via 32x32 tiled transpose (cols 0..1023)
__global__ void build_W2ts(const float* __restrict__ W2)
{
    __shared__ float t[32][33];
    const int kb = blockIdx.x * 32;
    const int jb = blockIdx.y * 32;
    const int tx = threadIdx.x & 31, ty = threadIdx.x >> 5;
#pragma unroll
    for (int r = 0; r < 4; r++) {
        const int k = kb + ty + r * 8;
        t[ty + r * 8][tx] = W2[(size_t)k * O_DIM + jb + tx];
    }
    __syncthreads();
#pragma unroll
    for (int r = 0; r < 4; r++) {
        const int j = jb + ty + r * 8;
        const int k = kb + tx;
        __nv_bfloat16 h, l;
        split_bf16(g_scale[k] * t[tx][ty + r * 8], h, l);
        g_W2t_hi[(size_t)j * H_DIM + k] = h;
        g_W2t_lo[(size_t)j * H_DIM + k] = l;
    }
}

// extra B^T columns 1024..1151: rel (scale.wrelc), conf (scale.wattc), zero pad
__global__ void build_Bextra()
{
    const int j = 1024 + blockIdx.x;
    const int k = blockIdx.y * 256 + threadIdx.x;
    const int j0 = j - 1024;
    float w = 0.f;
    if (j0 < R_DIM)       w = g_scale[k] * g_wrelc[k * R_DIM + j0];
    else if (j0 == R_DIM) w = g_scale[k] * g_wattc[k];
    __nv_bfloat16 h, l;
    split_bf16(w, h, l);
    g_W2t_hi[(size_t)j * H_DIM + k] = h;
    g_W2t_lo[(size_t)j * H_DIM + k] = l;
}

// bias2[j<1024] = b2[j] + sum_k shift[k] * W2[k][j]
__global__ void build_bias2(const float* __restrict__ W2, const float* __restrict__ b2)
{
    const int j = blockIdx.x * 256 + threadIdx.x;
    float s = b2[j];
#pragma unroll 4
    for (int k = 0; k < H_DIM; k++)
        s += g_shift[k] * W2[(size_t)k * O_DIM + j];
    g_bias2[j] = s;
}

// bias2[1024+j0]: rel -> bias2[:1024]@Wrel + brel ; conf -> bias2.watt + batt ; 0 pad
__global__ void build_biasX(const float* __restrict__ Wrel, const float* __restrict__ brel,
                            const float* __restrict__ watt, const float* __restrict__ batt)
{
    __shared__ float red[256];
    const int j0 = blockIdx.x, tid = threadIdx.x;
    float a = 0.f;
    if (j0 < R_DIM) {
        for (int o = tid; o < 1024; o += 256) a += g_bias2[o] * Wrel[(size_t)o * R_DIM + j0];
    } else if (j0 == R_DIM) {
        for (int o = tid; o < 1024; o += 256) a += g_bias2[o] * watt[o];
    }
    red[tid] = a;
    __syncthreads();
    for (int o = 128; o; o >>= 1) {
        if (tid < o) red[tid] += red[tid + o];
        __syncthreads();
    }
    if (tid == 0) {
        float b = 0.f;
        if (j0 < R_DIM)       b = red[0] + brel[j0];
        else if (j0 == R_DIM) b = red[0] + batt[0];
        g_bias2[1024 + j0] = b;
    }
}

// ---------------- BN stats from split planes (deterministic) -------------------
__global__ void stats_planes()
{
    const int cp = blockIdx.x * 256 + threadIdx.x;
    const int rb = blockIdx.y;
    const int c0 = cp * 2;
    float s0 = 0.f, s1 = 0.f, q0 = 0.f, q1 = 0.f;
#pragma unroll 4
    for (int r = 0; r < 256; r++) {
        const size_t o = (size_t)(rb * 256 + r) * H_DIM + c0;
        const __nv_bfloat162 h2 = *(const __nv_bfloat162*)(g_hb_hi + o);
        const __nv_bfloat162 l2 = *(const __nv_bfloat162*)(g_hb_lo + o);
        const float v0 = __bfloat162float(h2.x) + __bfloat162float(l2.x);
        const float v1 = __bfloat162float(h2.y) + __bfloat162float(l2.y);
        s0 += v0; q0 += v0 * v0;
        s1 += v1; q1 += v1 * v1;
    }
    g_ps[rb * H_DIM + c0] = s0; g_ps[rb * H_DIM + c0 + 1] = s1;
    g_pq[rb * H_DIM + c0] = q0; g_pq[rb * H_DIM + c0 + 1] = q1;
}

__global__ void finalize_bn(const float* __restrict__ gamma, const float* __restrict__ beta)
{
    const int c = blockIdx.x * 256 + threadIdx.x;
    float s = 0.f, q = 0.f;
#pragma unroll
    for (int i = 0; i < RB_STATS; i++) { s += g_ps[i * H_DIM + c]; q += g_pq[i * H_DIM + c]; }
    const float inv = 1.0f / (float)NP;
    const float mean = s * inv;
    const float var = q * inv - mean * mean;
    const float sc = gamma[c] * rsqrtf(var + BN_EPS);
    g_scale[c] = sc;
    g_shift[c] = beta[c] - mean * sc;
}

// ---------------- softmax + weighted aggregation -------------------------------
__global__ void attn_agg(const float* __restrict__ feat, float* __restrict__ enhanced)
{
    __shared__ float conf[N_OBJ];
    __shared__ float red[256];
    const int n = blockIdx.x, tid = threadIdx.x;
    const int c0 = blockIdx.y * 256;
    const float v = g_conf[n * N_OBJ + tid];
    red[tid] = v;
    __syncthreads();
    for (int o = 128; o; o >>= 1) {
        if (tid < o) red[tid] = fmaxf(red[tid], red[tid + o]);
        __syncthreads();
    }
    const float mx = red[0];
    __syncthreads();
    const float e = expf(v - mx);
    red[tid] = e;
    __syncthreads();
    for (int o = 128; o; o >>= 1) {
        if (tid < o) red[tid] += red[tid + o];
        __syncthreads();
    }
    const float p = e / red[0];
    __syncthreads();
    conf[tid] = p;
    __syncthreads();

    float acc = 0.f;
    const float* base = feat + (size_t)n * N_OBJ * O_DIM + c0 + tid;
#pragma unroll 4
    for (int m = 0; m < N_OBJ; m++)
        acc += conf[m] * base[(size_t)m * O_DIM];
    enhanced[(size_t)n * O_DIM + c0 + tid] = acc;
}

// ---------------- launcher ------------------------------------------------------
// NOTE: every kernel argument below is a d_in/d_out pointer. Device scratch is
// reached only through device-code symbol references.
extern "C" void kernel_launch(void* const* d_in, const int* in_sizes, int n_in,
                              void* d_out, int out_size)
{
    const float* feats = (const float*)d_in[0];
    const float* cemb  = (const float*)d_in[1];
    const float* W1    = (const float*)d_in[2];
    const float* b1    = (const float*)d_in[3];
    const float* gamma = (const float*)d_in[4];
    const float* beta  = (const float*)d_in[5];
    const float* W2    = (const float*)d_in[6];
    const float* b2    = (const float*)d_in[7];
    const float* watt  = (const float*)d_in[8];
    const float* batt  = (const float*)d_in[9];
    const float* Wrel  = (const float*)d_in[10];
    const float* brel  = (const float*)d_in[11];

    float* out      = (float*)d_out;
    float* feat     = out;
    float* enhanced = out + (size_t)NP * O_DIM;
    float* relation = enhanced + (size_t)N_OBJ * O_DIM;

    // converters + small mats (independent of GEMMs)
    convert_cemb<<<(int)(((size_t)NP * C_EMB / 4 + 255) / 256), 256>>>(cemb);
    split_W1t<<<dim3(C_EMB / 32, H_DIM / 32), 256>>>(W1);
    small_mats<<<H_DIM, 256>>>(W2, Wrel, watt);

    // hi/hj: K-split GEMM + deterministic reduce
    gemm_hij<<<dim3(8, 2, 8), 256>>>(feats, W1);
    reduce_hij<<<2 * N_OBJ * H_DIM / 256, 256>>>();

    // GEMM1 (HMMA): h = leakyrelu(cemb @ W1c + hi + hj + b1) -> split planes
    mma_gemm<1><<<dim3(8, 512), 256>>>(b1, nullptr, nullptr);

    // BN stats + fold into combined B / bias
    stats_planes<<<dim3(2, RB_STATS), 256>>>();
    finalize_bn<<<4, 256>>>(gamma, beta);
    build_W2ts<<<dim3(H_DIM / 32, O_DIM / 32), 256>>>(W2);
    build_Bextra<<<dim3(128, 4), 256>>>();
    build_bias2<<<O_DIM / 256, 256>>>(W2, b2);
    build_biasX<<<128, 256>>>(Wrel, brel, watt, batt);

    // GEMM2 (HMMA): [feat | relation | conf] = h @ Bcomb + bias2
    mma_gemm<0><<<dim3(9, 512), 256>>>(nullptr, feat, relation);

    // attention softmax + aggregation (logits from GEMM2)
    attn_agg<<<dim3(N_OBJ, 4), 256>>>(feat, enhanced);
}

// round 14
// speedup vs baseline: 1.0997x; 1.0407x over previous
#include <cuda_runtime.h>
#include <cuda_bf16.h>
#include <cstdint>
#include <math.h>

#define N_OBJ 256
#define D_IN  1024
#define C_EMB 256
#define H_DIM 1024
#define O_DIM 1024
#define R_DIM 51
#define NP    (N_OBJ * N_OBJ)   /* 65536 edge rows */
#define BN_EPS 1e-5f
#define SLOPE  0.01f
#define RB_STATS 256
#define N2TOT 1152               /* 1024 feat + 51 rel + 1 conf + 76 pad */

// ---------------- scratch (static device globals; no allocation) ---------------
// RULE (root cause of rounds 2-8): these symbols are ONLY referenced inside
// device code. NEVER passed as kernel arguments from kernel_launch (host code
// would pass the host shadow address; ATS on GB300 makes it read zeros).
__device__ __align__(128) __nv_bfloat16 g_c_hi[(size_t)NP * C_EMB];   // cemb split
__device__ __align__(128) __nv_bfloat16 g_c_lo[(size_t)NP * C_EMB];
__device__ __align__(128) __nv_bfloat16 g_W1t_hi[H_DIM * C_EMB];      // W1c^T split [j][k]
__device__ __align__(128) __nv_bfloat16 g_W1t_lo[H_DIM * C_EMB];
__device__ __align__(128) __nv_bfloat16 g_hb_hi[(size_t)NP * H_DIM];  // h split (pre-BN)
__device__ __align__(128) __nv_bfloat16 g_hb_lo[(size_t)NP * H_DIM];
__device__ __align__(128) __nv_bfloat16 g_W2t_hi[(size_t)N2TOT * H_DIM]; // combined B^T split
__device__ __align__(128) __nv_bfloat16 g_W2t_lo[(size_t)N2TOT * H_DIM];
__device__ float g_hi[N_OBJ * H_DIM];
__device__ float g_hj[N_OBJ * H_DIM];
__device__ float g_part[8 * N_OBJ * H_DIM];   // K-split partials for hi/hj
__device__ float g_ps[RB_STATS * H_DIM];
__device__ float g_pq[RB_STATS * H_DIM];
__device__ float g_scale[H_DIM];
__device__ float g_shift[H_DIM];
__device__ float g_bias2[N2TOT];              // [b2+shift.W2 | rel bias | conf bias | 0]
__device__ float g_wrelc[H_DIM * R_DIM];      // W2 @ W_rel
__device__ float g_wattc[H_DIM];              // W2 @ w_att
__device__ float g_conf[NP];                  // attention logits

__device__ __forceinline__ void mma_bf16(float* c, const uint32_t* a, const uint32_t* b) {
    asm volatile("mma.sync.aligned.m16n8k16.row.col.f32.bf16.bf16.f32 "
                 "{%0,%1,%2,%3}, {%4,%5,%6,%7}, {%8,%9}, {%0,%1,%2,%3};"
                 : "+f"(c[0]), "+f"(c[1]), "+f"(c[2]), "+f"(c[3])
                 : "r"(a[0]), "r"(a[1]), "r"(a[2]), "r"(a[3]), "r"(b[0]), "r"(b[1]));
}
__device__ __forceinline__ void split_bf16(float v, __nv_bfloat16& h, __nv_bfloat16& l) {
    h = __float2bfloat16_rn(v);
    l = __float2bfloat16_rn(v - __bfloat162float(h));
}
__device__ __forceinline__ uint32_t smem_u32(const void* p) {
    uint32_t a;
    asm("{ .reg .u64 t; cvta.to.shared.u64 t, %1; cvt.u32.u64 %0, t; }" : "=r"(a) : "l"(p));
    return a;
}
__device__ __forceinline__ void cp16(uint32_t s, const void* g) {
    asm volatile("cp.async.cg.shared.global [%0], [%1], 16;" :: "r"(s), "l"(g));
}
#define CP_COMMIT() asm volatile("cp.async.commit_group;" ::: "memory")
#define CP_WAIT0()  asm volatile("cp.async.wait_group 0;" ::: "memory")

// ---------------- HMMA bf16x3 GEMM (cp.async; 2 CTAs/SM via launch bounds) -----
// EPI 1: h = leakyrelu(cemb @ W1c + g_hi[nn]+g_hj[mm]+bias) -> split planes  K=256
// EPI 0: [feat | rel | conf] = h @ Bcomb + g_bias2                           K=1024
// B fragments loaded per-nt inside the MMA loop to keep live regs <= 128 so
// two CTAs co-reside per SM (hides syncthreads + smem-load latency).
#define TK2   16
#define APAD2 24
template<int EPI>
__global__ __launch_bounds__(256, 2)
void mma_gemm(const float* __restrict__ bias,
              float* __restrict__ out_feat,
              float* __restrict__ out_rel)
{
    const __nv_bfloat16* __restrict__ Ahi = (EPI == 1) ? g_c_hi : g_hb_hi;
    const __nv_bfloat16* __restrict__ Alo = (EPI == 1) ? g_c_lo : g_hb_lo;
    const __nv_bfloat16* __restrict__ Bhi = (EPI == 1) ? g_W1t_hi : g_W2t_hi;
    const __nv_bfloat16* __restrict__ Blo = (EPI == 1) ? g_W1t_lo : g_W2t_lo;
    constexpr int K = (EPI == 1) ? C_EMB : H_DIM;
    constexpr int NC = K / TK2;

    __shared__ __align__(16) __nv_bfloat16 sAhi[2][128][APAD2];
    __shared__ __align__(16) __nv_bfloat16 sAlo[2][128][APAD2];
    __shared__ __align__(16) __nv_bfloat16 sBhi[2][128][APAD2];
    __shared__ __align__(16) __nv_bfloat16 sBlo[2][128][APAD2];

    const int tid = threadIdx.x;
    const int lane = tid & 31, wid = tid >> 5;
    const int m0 = blockIdx.y * 128, n0 = blockIdx.x * 128;

    const int m_base = (wid >> 2) * 64;
    const int n_base = (wid & 3) * 32;
    const int fr = lane >> 2;             // fragment row 0..7
    const int fk = (lane & 3) * 2;        // fragment k 0,2,4,6

    const int ld_row = tid >> 1, ld_c = (tid & 1) * 8;

    // cp.async loader: one 16B granule per plane per thread per chunk
    auto load_chunk = [&](int c, int s) {
        const size_t ka = (size_t)(m0 + ld_row) * K + c * TK2 + ld_c;
        const size_t kb = (size_t)(n0 + ld_row) * K + c * TK2 + ld_c;
        cp16(smem_u32(&sAhi[s][ld_row][ld_c]), Ahi + ka);
        cp16(smem_u32(&sAlo[s][ld_row][ld_c]), Alo + ka);
        cp16(smem_u32(&sBhi[s][ld_row][ld_c]), Bhi + kb);
        cp16(smem_u32(&sBlo[s][ld_row][ld_c]), Blo + kb);
    };

    float acc[4][4][4];
#pragma unroll
    for (int i = 0; i < 4; i++)
#pragma unroll
        for (int j = 0; j < 4; j++)
#pragma unroll
            for (int r = 0; r < 4; r++) acc[i][j][r] = 0.f;

    load_chunk(0, 0);
    CP_COMMIT();

    for (int c = 0; c < NC; c++) {
        const int cur = c & 1, nxt = cur ^ 1;
        CP_WAIT0();          // drain chunk c (sole pending group)
        __syncthreads();     // all threads see buffer cur; nxt free to overwrite
        if (c + 1 < NC) load_chunk(c + 1, nxt);
        CP_COMMIT();         // overlaps with compute below

        uint32_t a_hi[4][4], a_lo[4][4];
#pragma unroll
        for (int mt = 0; mt < 4; mt++) {
            const int r0 = m_base + mt * 16 + fr;
            a_hi[mt][0] = *(const uint32_t*)&sAhi[cur][r0    ][fk];
            a_hi[mt][1] = *(const uint32_t*)&sAhi[cur][r0 + 8][fk];
            a_hi[mt][2] = *(const uint32_t*)&sAhi[cur][r0    ][fk + 8];
            a_hi[mt][3] = *(const uint32_t*)&sAhi[cur][r0 + 8][fk + 8];
            a_lo[mt][0] = *(const uint32_t*)&sAlo[cur][r0    ][fk];
            a_lo[mt][1] = *(const uint32_t*)&sAlo[cur][r0 + 8][fk];
            a_lo[mt][2] = *(const uint32_t*)&sAlo[cur][r0    ][fk + 8];
            a_lo[mt][3] = *(const uint32_t*)&sAlo[cur][r0 + 8][fk + 8];
        }
#pragma unroll
        for (int nt = 0; nt < 4; nt++) {
            const int n = n_base + nt * 8 + fr;
            uint32_t b_hi[2], b_lo[2];
            b_hi[0] = *(const uint32_t*)&sBhi[cur][n][fk];
            b_hi[1] = *(const uint32_t*)&sBhi[cur][n][fk + 8];
            b_lo[0] = *(const uint32_t*)&sBlo[cur][n][fk];
            b_lo[1] = *(const uint32_t*)&sBlo[cur][n][fk + 8];
#pragma unroll
            for (int mt = 0; mt < 4; mt++) {
                mma_bf16(acc[mt][nt], a_hi[mt], b_hi);
                mma_bf16(acc[mt][nt], a_hi[mt], b_lo);
                mma_bf16(acc[mt][nt], a_lo[mt], b_hi);
            }
        }
        __syncthreads();     // done reading cur before it is refilled at c+2
    }

    // epilogue: c0,c1 -> row fr; c2,c3 -> row fr+8
#pragma unroll
    for (int mt = 0; mt < 4; mt++)
#pragma unroll
        for (int nt = 0; nt < 4; nt++) {
            const int col0 = n0 + n_base + nt * 8 + fk;
#pragma unroll
            for (int half = 0; half < 2; half++) {
                const int row = m0 + m_base + mt * 16 + fr + half * 8;
                float v0 = acc[mt][nt][half * 2];
                float v1 = acc[mt][nt][half * 2 + 1];
                if (EPI == 1) {
                    const int nn = row >> 8, mm = row & 255;
                    v0 += g_hi[nn * H_DIM + col0]     + g_hj[mm * H_DIM + col0]     + bias[col0];
                    v1 += g_hi[nn * H_DIM + col0 + 1] + g_hj[mm * H_DIM + col0 + 1] + bias[col0 + 1];
                    v0 = (v0 >= 0.f) ? v0 : SLOPE * v0;
                    v1 = (v1 >= 0.f) ? v1 : SLOPE * v1;
                    __nv_bfloat16 h0, l0, h1, l1;
                    split_bf16(v0, h0, l0);
                    split_bf16(v1, h1, l1);
                    const size_t o = (size_t)row * H_DIM + col0;
                    *(__nv_bfloat162*)(g_hb_hi + o) = __nv_bfloat162(h0, h1);
                    *(__nv_bfloat162*)(g_hb_lo + o) = __nv_bfloat162(l0, l1);
                } else {
                    v0 += g_bias2[col0];
                    v1 += g_bias2[col0 + 1];
                    if (blockIdx.x < 8) {
                        *(float2*)(out_feat + (size_t)row * O_DIM + col0) = make_float2(v0, v1);
                    } else {
                        const int j0 = col0 - 1024;   // even
                        if (j0 < R_DIM)           out_rel[(size_t)row * R_DIM + j0] = v0;
                        if (j0 + 1 < R_DIM)       out_rel[(size_t)row * R_DIM + j0 + 1] = v1;
                        else if (j0 + 1 == R_DIM) g_conf[row] = v1;
                    }
                }
            }
        }
}

// ---------------- hi/hj: K-split fp32 GEMM (128 blocks) + reduce ---------------
__launch_bounds__(256)
__global__ void gemm_hij(const float* __restrict__ feats, const float* __restrict__ W1)
{
    const int which = blockIdx.z >> 2;
    const int kc = blockIdx.z & 3;
    __shared__ float As[8][132];
    __shared__ float Bs[8][128];
    const int tid = threadIdx.x;
    const int tx = tid & 15, ty = tid >> 4;
    const int m0 = blockIdx.y * 128, n0 = blockIdx.x * 128;
    float acc[8][8];
#pragma unroll
    for (int i = 0; i < 8; i++)
#pragma unroll
        for (int j = 0; j < 8; j++) acc[i][j] = 0.f;
    const int ar = tid >> 1, ak = (tid & 1) * 4;
    const int bk = tid >> 5, bc = (tid & 31) * 4;
    const float* Aptr = feats + (size_t)(m0 + ar) * 1024 + kc * 256 + ak;
    const float* Bptr = W1 + (size_t)(which * D_IN + kc * 256 + bk) * 1024 + n0 + bc;
    for (int k0 = 0; k0 < 256; k0 += 8) {
        float4 av = *(const float4*)(Aptr + k0);
        float4 bv = *(const float4*)(Bptr + (size_t)k0 * 1024);
        As[ak][ar] = av.x; As[ak + 1][ar] = av.y; As[ak + 2][ar] = av.z; As[ak + 3][ar] = av.w;
        *(float4*)(&Bs[bk][bc]) = bv;
        __syncthreads();
#pragma unroll
        for (int kk = 0; kk < 8; kk++) {
            float a[8], b[8];
#pragma unroll
            for (int i = 0; i < 8; i++) a[i] = As[kk][ty * 8 + i];
#pragma unroll
            for (int j = 0; j < 8; j++) b[j] = Bs[kk][tx * 8 + j];
#pragma unroll
            for (int i = 0; i < 8; i++)
#pragma unroll
                for (int j = 0; j < 8; j++) acc[i][j] += a[i] * b[j];
        }
        __syncthreads();
    }
    float* dst = g_part + (size_t)blockIdx.z * N_OBJ * H_DIM;
#pragma unroll
    for (int i = 0; i < 8; i++)
#pragma unroll
        for (int j = 0; j < 8; j++)
            dst[(size_t)(m0 + ty * 8 + i) * 1024 + n0 + tx * 8 + j] = acc[i][j];
}

__global__ void reduce_hij()
{
    const int idx = blockIdx.x * 256 + threadIdx.x;
    const int which = idx >> 18;
    const int base = idx & (N_OBJ * H_DIM - 1);
    const size_t stride = (size_t)N_OBJ * H_DIM;
    const float* p = g_part + (size_t)which * 4 * stride + base;
    const float s = p[0] + p[stride] + p[2 * stride] + p[3 * stride];
    if (which == 0) g_hi[base] = s;
    else            g_hj[base] = s;
}

// ---------------- converters ---------------------------------------------------
__global__ void convert_cemb(const float* __restrict__ in)
{
    const size_t i = ((size_t)blockIdx.x * 256 + threadIdx.x) * 4;
    if (i >= (size_t)NP * C_EMB) return;
    const float4 v4 = *(const float4*)(in + i);
    const float v[4] = { v4.x, v4.y, v4.z, v4.w };
    uint32_t hw[2], lw[2];
#pragma unroll
    for (int p = 0; p < 2; p++) {
        __nv_bfloat16 h0, l0, h1, l1;
        split_bf16(v[2 * p], h0, l0);
        split_bf16(v[2 * p + 1], h1, l1);
        hw[p] = (uint32_t)__bfloat16_as_ushort(h0) | ((uint32_t)__bfloat16_as_ushort(h1) << 16);
        lw[p] = (uint32_t)__bfloat16_as_ushort(l0) | ((uint32_t)__bfloat16_as_ushort(l1) << 16);
    }
    *(uint2*)((char*)g_c_hi + i * 2) = make_uint2(hw[0], hw[1]);
    *(uint2*)((char*)g_c_lo + i * 2) = make_uint2(lw[0], lw[1]);
}

// W1c^T split via 32x32 tiled transpose. grid (C_EMB/32, H_DIM/32), 256 thr.
__global__ void split_W1t(const float* __restrict__ W1)
{
    __shared__ float t[32][33];
    const int kb = blockIdx.x * 32;
    const int jb = blockIdx.y * 32;
    const int tx = threadIdx.x & 31, ty = threadIdx.x >> 5;
#pragma unroll
    for (int r = 0; r < 4; r++) {
        const int k = kb + ty + r * 8;
        t[ty + r * 8][tx] = W1[(size_t)(2 * D_IN + k) * H_DIM + jb + tx];
    }
    __syncthreads();
#pragma unroll
    for (int r = 0; r < 4; r++) {
        const int j = jb + ty + r * 8;
        const int k = kb + tx;
        __nv_bfloat16 h, l;
        split_bf16(t[tx][ty + r * 8], h, l);
        g_W1t_hi[(size_t)j * C_EMB + k] = h;
        g_W1t_lo[(size_t)j * C_EMB + k] = l;
    }
}

// wrelc = W2 @ W_rel [1024,51], wattc = W2 @ w_att [1024]  (one block per k-row)
__global__ void small_mats(const float* __restrict__ W2, const float* __restrict__ Wrel,
                           const float* __restrict__ watt)
{
    __shared__ float row[1024];
    const int i = blockIdx.x, tid = threadIdx.x;
    for (int o = tid; o < 1024; o += 256) row[o] = W2[(size_t)i * O_DIM + o];
    __syncthreads();
    if (tid < R_DIM) {
        float s = 0.f;
        for (int o = 0; o < 1024; o++) s += row[o] * Wrel[(size_t)o * R_DIM + tid];
        g_wrelc[i * R_DIM + tid] = s;
    } else if (tid == R_DIM) {
        float s = 0.f;
        for (int o = 0; o < 1024; o++) s += row[o] * watt[o];
        g_wattc[i] = s;
    }
}

// (scale.W2)^T split via 32x32 tiled transpose (cols 0..1023)
__global__ void build_W2ts(const float* __restrict__ W2)
{
    __shared__ float t[32][33];
    const int kb = blockIdx.x * 32;
    const int jb = blockIdx.y * 32;
    const int tx = threadIdx.x & 31, ty = threadIdx.x >> 5;
#pragma unroll
    for (int r = 0; r < 4; r++) {
        const int k = kb + ty + r * 8;
        t[ty + r * 8][tx] = W2[(size_t)k * O_DIM + jb + tx];
    }
    __syncthreads();
#pragma unroll
    for (int r = 0; r < 4; r++) {
        const int j = jb + ty + r * 8;
        const int k = kb + tx;
        __nv_bfloat16 h, l;
        split_bf16(g_scale[k] * t[tx][ty + r * 8], h, l);
        g_W2t_hi[(size_t)j * H_DIM + k] = h;
        g_W2t_lo[(size_t)j * H_DIM + k] = l;
    }
}

// extra B^T columns 1024..1151: rel (scale.wrelc), conf (scale.wattc), zero pad
__global__ void build_Bextra()
{
    const int j = 1024 + blockIdx.x;
    const int k = blockIdx.y * 256 + threadIdx.x;
    const int j0 = j - 1024;
    float w = 0.f;
    if (j0 < R_DIM)       w = g_scale[k] * g_wrelc[k * R_DIM + j0];
    else if (j0 == R_DIM) w = g_scale[k] * g_wattc[k];
    __nv_bfloat16 h, l;
    split_bf16(w, h, l);
    g_W2t_hi[(size_t)j * H_DIM + k] = h;
    g_W2t_lo[(size_t)j * H_DIM + k] = l;
}

// bias2[j<1024] = b2[j] + sum_k shift[k] * W2[k][j]
__global__ void build_bias2(const float* __restrict__ W2, const float* __restrict__ b2)
{
    const int j = blockIdx.x * 256 + threadIdx.x;
    float s = b2[j];
#pragma unroll 4
    for (int k = 0; k < H_DIM; k++)
        s += g_shift[k] * W2[(size_t)k * O_DIM + j];
    g_bias2[j] = s;
}

// bias2[1024+j0]: rel -> bias2[:1024]@Wrel + brel ; conf -> bias2.watt + batt ; 0 pad
__global__ void build_biasX(const float* __restrict__ Wrel, const float* __restrict__ brel,
                            const float* __restrict__ watt, const float* __restrict__ batt)
{
    __shared__ float red[256];
    const int j0 = blockIdx.x, tid = threadIdx.x;
    float a = 0.f;
    if (j0 < R_DIM) {
        for (int o = tid; o < 1024; o += 256) a += g_bias2[o] * Wrel[(size_t)o * R_DIM + j0];
    } else if (j0 == R_DIM) {
        for (int o = tid; o < 1024; o += 256) a += g_bias2[o] * watt[o];
    }
    red[tid] = a;
    __syncthreads();
    for (int o = 128; o; o >>= 1) {
        if (tid < o) red[tid] += red[tid + o];
        __syncthreads();
    }
    if (tid == 0) {
        float b = 0.f;
        if (j0 < R_DIM)       b = red[0] + brel[j0];
        else if (j0 == R_DIM) b = red[0] + batt[0];
        g_bias2[1024 + j0] = b;
    }
}

// ---------------- BN stats from split planes (deterministic) -------------------
__global__ void stats_planes()
{
    const int cp = blockIdx.x * 256 + threadIdx.x;
    const int rb = blockIdx.y;
    const int c0 = cp * 2;
    float s0 = 0.f, s1 = 0.f, q0 = 0.f, q1 = 0.f;
#pragma unroll 4
    for (int r = 0; r < 256; r++) {
        const size_t o = (size_t)(rb * 256 + r) * H_DIM + c0;
        const __nv_bfloat162 h2 = *(const __nv_bfloat162*)(g_hb_hi + o);
        const __nv_bfloat162 l2 = *(const __nv_bfloat162*)(g_hb_lo + o);
        const float v0 = __bfloat162float(h2.x) + __bfloat162float(l2.x);
        const float v1 = __bfloat162float(h2.y) + __bfloat162float(l2.y);
        s0 += v0; q0 += v0 * v0;
        s1 += v1; q1 += v1 * v1;
    }
    g_ps[rb * H_DIM + c0] = s0; g_ps[rb * H_DIM + c0 + 1] = s1;
    g_pq[rb * H_DIM + c0] = q0; g_pq[rb * H_DIM + c0 + 1] = q1;
}

__global__ void finalize_bn(const float* __restrict__ gamma, const float* __restrict__ beta)
{
    const int c = blockIdx.x * 256 + threadIdx.x;
    float s = 0.f, q = 0.f;
#pragma unroll
    for (int i = 0; i < RB_STATS; i++) { s += g_ps[i * H_DIM + c]; q += g_pq[i * H_DIM + c]; }
    const float inv = 1.0f / (float)NP;
    const float mean = s * inv;
    const float var = q * inv - mean * mean;
    const float sc = gamma[c] * rsqrtf(var + BN_EPS);
    g_scale[c] = sc;
    g_shift[c] = beta[c] - mean * sc;
}

// ---------------- softmax + weighted aggregation -------------------------------
__global__ void attn_agg(const float* __restrict__ feat, float* __restrict__ enhanced)
{
    __shared__ float conf[N_OBJ];
    __shared__ float red[256];
    const int n = blockIdx.x, tid = threadIdx.x;
    const int c0 = blockIdx.y * 256;
    const float v = g_conf[n * N_OBJ + tid];
    red[tid] = v;
    __syncthreads();
    for (int o = 128; o; o >>= 1) {
        if (tid < o) red[tid] = fmaxf(red[tid], red[tid + o]);
        __syncthreads();
    }
    const float mx = red[0];
    __syncthreads();
    const float e = expf(v - mx);
    red[tid] = e;
    __syncthreads();
    for (int o = 128; o; o >>= 1) {
        if (tid < o) red[tid] += red[tid + o];
        __syncthreads();
    }
    const float p = e / red[0];
    __syncthreads();
    conf[tid] = p;
    __syncthreads();

    float acc = 0.f;
    const float* base = feat + (size_t)n * N_OBJ * O_DIM + c0 + tid;
#pragma unroll 4
    for (int m = 0; m < N_OBJ; m++)
        acc += conf[m] * base[(size_t)m * O_DIM];
    enhanced[(size_t)n * O_DIM + c0 + tid] = acc;
}

// ---------------- launcher ------------------------------------------------------
// NOTE: every kernel argument below is a d_in/d_out pointer. Device scratch is
// reached only through device-code symbol references.
extern "C" void kernel_launch(void* const* d_in, const int* in_sizes, int n_in,
                              void* d_out, int out_size)
{
    const float* feats = (const float*)d_in[0];
    const float* cemb  = (const float*)d_in[1];
    const float* W1    = (const float*)d_in[2];
    const float* b1    = (const float*)d_in[3];
    const float* gamma = (const float*)d_in[4];
    const float* beta  = (const float*)d_in[5];
    const float* W2    = (const float*)d_in[6];
    const float* b2    = (const float*)d_in[7];
    const float* watt  = (const float*)d_in[8];
    const float* batt  = (const float*)d_in[9];
    const float* Wrel  = (const float*)d_in[10];
    const float* brel  = (const float*)d_in[11];

    float* out      = (float*)d_out;
    float* feat     = out;
    float* enhanced = out + (size_t)NP * O_DIM;
    float* relation = enhanced + (size_t)N_OBJ * O_DIM;

    // converters + small mats (independent of GEMMs)
    convert_cemb<<<(int)(((size_t)NP * C_EMB / 4 + 255) / 256), 256>>>(cemb);
    split_W1t<<<dim3(C_EMB / 32, H_DIM / 32), 256>>>(W1);
    small_mats<<<H_DIM, 256>>>(W2, Wrel, watt);

    // hi/hj: K-split GEMM + deterministic reduce
    gemm_hij<<<dim3(8, 2, 8), 256>>>(feats, W1);
    reduce_hij<<<2 * N_OBJ * H_DIM / 256, 256>>>();

    // GEMM1 (HMMA): h = leakyrelu(cemb @ W1c + hi + hj + b1) -> split planes
    mma_gemm<1><<<dim3(8, 512), 256>>>(b1, nullptr, nullptr);

    // BN stats + fold into combined B / bias
    stats_planes<<<dim3(2, RB_STATS), 256>>>();
    finalize_bn<<<4, 256>>>(gamma, beta);
    build_W2ts<<<dim3(H_DIM / 32, O_DIM / 32), 256>>>(W2);
    build_Bextra<<<dim3(128, 4), 256>>>();
    build_bias2<<<O_DIM / 256, 256>>>(W2, b2);
    build_biasX<<<128, 256>>>(Wrel, brel, watt, batt);

    // GEMM2 (HMMA): [feat | relation | conf] = h @ Bcomb + bias2
    mma_gemm<0><<<dim3(9, 512), 256>>>(nullptr, feat, relation);

    // attention softmax + aggregation (logits from GEMM2)
    attn_agg<<<dim3(N_OBJ, 4), 256>>>(feat, enhanced);
}

// round 15
// speedup vs baseline: 1.2474x; 1.1343x over previous
#include <cuda_runtime.h>
#include <cuda_bf16.h>
#include <cstdint>
#include <math.h>

#define N_OBJ 256
#define D_IN  1024
#define C_EMB 256
#define H_DIM 1024
#define O_DIM 1024
#define R_DIM 51
#define NP    (N_OBJ * N_OBJ)   /* 65536 edge rows */
#define BN_EPS 1e-5f
#define SLOPE  0.01f
#define RB_STATS 256
#define N2TOT 1152               /* 1024 feat + 51 rel + 1 conf + 76 pad */

// ---------------- scratch (static device globals; no allocation) ---------------
// RULE (root cause of rounds 2-8): these symbols are ONLY referenced inside
// device code. NEVER passed as kernel arguments from kernel_launch (host code
// would pass the host shadow address; ATS on GB300 makes it read zeros).
__device__ __align__(128) __nv_bfloat16 g_c_hi[(size_t)NP * C_EMB];   // cemb split
__device__ __align__(128) __nv_bfloat16 g_c_lo[(size_t)NP * C_EMB];
__device__ __align__(128) __nv_bfloat16 g_W1t_hi[H_DIM * C_EMB];      // W1c^T split [j][k]
__device__ __align__(128) __nv_bfloat16 g_W1t_lo[H_DIM * C_EMB];
__device__ __align__(128) __nv_bfloat16 g_hb_hi[(size_t)NP * H_DIM];  // h split (pre-BN)
__device__ __align__(128) __nv_bfloat16 g_hb_lo[(size_t)NP * H_DIM];
__device__ __align__(128) __nv_bfloat16 g_W2t_hi[(size_t)N2TOT * H_DIM]; // combined B^T split
__device__ __align__(128) __nv_bfloat16 g_W2t_lo[(size_t)N2TOT * H_DIM];
__device__ float g_hi[N_OBJ * H_DIM];
__device__ float g_hj[N_OBJ * H_DIM];
__device__ float g_part[8 * N_OBJ * H_DIM];   // K-split partials for hi/hj
__device__ float g_ps[RB_STATS * H_DIM];
__device__ float g_pq[RB_STATS * H_DIM];
__device__ float g_scale[H_DIM];
__device__ float g_shift[H_DIM];
__device__ float g_bias2[N2TOT];              // [b2+shift.W2 | rel bias | conf bias | 0]
__device__ float g_wrelc[H_DIM * R_DIM];      // W2 @ W_rel
__device__ float g_wattc[H_DIM];              // W2 @ w_att
__device__ float g_conf[NP];                  // attention logits

__device__ __forceinline__ void mma_bf16(float* c, const uint32_t* a, const uint32_t* b) {
    asm volatile("mma.sync.aligned.m16n8k16.row.col.f32.bf16.bf16.f32 "
                 "{%0,%1,%2,%3}, {%4,%5,%6,%7}, {%8,%9}, {%0,%1,%2,%3};"
                 : "+f"(c[0]), "+f"(c[1]), "+f"(c[2]), "+f"(c[3])
                 : "r"(a[0]), "r"(a[1]), "r"(a[2]), "r"(a[3]), "r"(b[0]), "r"(b[1]));
}
__device__ __forceinline__ void split_bf16(float v, __nv_bfloat16& h, __nv_bfloat16& l) {
    h = __float2bfloat16_rn(v);
    l = __float2bfloat16_rn(v - __bfloat162float(h));
}
__device__ __forceinline__ uint32_t smem_u32(const void* p) {
    uint32_t a;
    asm("{ .reg .u64 t; cvta.to.shared.u64 t, %1; cvt.u32.u64 %0, t; }" : "=r"(a) : "l"(p));
    return a;
}
__device__ __forceinline__ void cp16(uint32_t s, const void* g) {
    asm volatile("cp.async.cg.shared.global [%0], [%1], 16;" :: "r"(s), "l"(g));
}
#define CP_COMMIT() asm volatile("cp.async.commit_group;" ::: "memory")
#define CP_WAIT0()  asm volatile("cp.async.wait_group 0;" ::: "memory")

// ---------------- HMMA bf16x3 GEMM (cp.async; 2 CTAs/SM; TKP-templated) --------
// EPI 1: h = leakyrelu(cemb @ W1c + g_hi[nn]+g_hj[mm]+bias) -> split planes  K=256
// EPI 0: [feat | rel | conf] = h @ Bcomb + g_bias2                           K=1024
// TKP=32 (80KB dynamic smem, needs opt-in) halves iteration count / syncs.
// TKP=16 (48KB dynamic, no opt-in needed) is the host-side fallback.
template<int EPI, int TKP>
__global__ __launch_bounds__(256, 2)
void mma_gemm(const float* __restrict__ bias,
              float* __restrict__ out_feat,
              float* __restrict__ out_rel)
{
    constexpr int APAD = TKP + 8;
    constexpr int PLANE = 2 * 128 * APAD;      // elements per plane (2 stages)
    extern __shared__ __align__(16) __nv_bfloat16 dsm[];
    __nv_bfloat16* const sAhi = dsm;
    __nv_bfloat16* const sAlo = dsm + PLANE;
    __nv_bfloat16* const sBhi = dsm + 2 * PLANE;
    __nv_bfloat16* const sBlo = dsm + 3 * PLANE;

    const __nv_bfloat16* __restrict__ Ahi = (EPI == 1) ? g_c_hi : g_hb_hi;
    const __nv_bfloat16* __restrict__ Alo = (EPI == 1) ? g_c_lo : g_hb_lo;
    const __nv_bfloat16* __restrict__ Bhi = (EPI == 1) ? g_W1t_hi : g_W2t_hi;
    const __nv_bfloat16* __restrict__ Blo = (EPI == 1) ? g_W1t_lo : g_W2t_lo;
    constexpr int K = (EPI == 1) ? C_EMB : H_DIM;
    constexpr int NC = K / TKP;
    constexpr int GPP = TKP / 8;               // 16B granules per row per plane

    const int tid = threadIdx.x;
    const int lane = tid & 31, wid = tid >> 5;
    const int m0 = blockIdx.y * 128, n0 = blockIdx.x * 128;

    const int m_base = (wid >> 2) * 64;
    const int n_base = (wid & 3) * 32;
    const int fr = lane >> 2;             // fragment row 0..7
    const int fk = (lane & 3) * 2;        // fragment k 0,2,4,6

    // cp.async loader for one chunk
    auto load_chunk = [&](int c, int s) {
#pragma unroll
        for (int it = 0; it < TKP / 16; it++) {
            const int g = tid + it * 256;
            const int row = g / GPP;
            const int c16 = g % GPP;
            const size_t ka = (size_t)(m0 + row) * K + c * TKP + c16 * 8;
            const size_t kb = (size_t)(n0 + row) * K + c * TKP + c16 * 8;
            const uint32_t so = (uint32_t)(((s * 128 + row) * APAD + c16 * 8) * 2);
            cp16(smem_u32(sAhi) + so, Ahi + ka);
            cp16(smem_u32(sAlo) + so, Alo + ka);
            cp16(smem_u32(sBhi) + so, Bhi + kb);
            cp16(smem_u32(sBlo) + so, Blo + kb);
        }
    };

    float acc[4][4][4];
#pragma unroll
    for (int i = 0; i < 4; i++)
#pragma unroll
        for (int j = 0; j < 4; j++)
#pragma unroll
            for (int r = 0; r < 4; r++) acc[i][j][r] = 0.f;

    load_chunk(0, 0);
    CP_COMMIT();

    for (int c = 0; c < NC; c++) {
        const int cur = c & 1, nxt = cur ^ 1;
        CP_WAIT0();          // drain chunk c (sole pending group)
        __syncthreads();     // all threads see buffer cur; nxt free to overwrite
        if (c + 1 < NC) load_chunk(c + 1, nxt);
        CP_COMMIT();         // overlaps with compute below

#pragma unroll
        for (int ks = 0; ks < TKP / 16; ks++) {
            const int kb = ks * 16;
            uint32_t a_hi[4][4], a_lo[4][4];
#pragma unroll
            for (int mt = 0; mt < 4; mt++) {
                const int r0 = m_base + mt * 16 + fr;
                const int base0 = (cur * 128 + r0) * APAD + kb + fk;
                a_hi[mt][0] = *(const uint32_t*)&sAhi[base0];
                a_hi[mt][1] = *(const uint32_t*)&sAhi[base0 + 8 * APAD];
                a_hi[mt][2] = *(const uint32_t*)&sAhi[base0 + 8];
                a_hi[mt][3] = *(const uint32_t*)&sAhi[base0 + 8 * APAD + 8];
                a_lo[mt][0] = *(const uint32_t*)&sAlo[base0];
                a_lo[mt][1] = *(const uint32_t*)&sAlo[base0 + 8 * APAD];
                a_lo[mt][2] = *(const uint32_t*)&sAlo[base0 + 8];
                a_lo[mt][3] = *(const uint32_t*)&sAlo[base0 + 8 * APAD + 8];
            }
#pragma unroll
            for (int nt = 0; nt < 4; nt++) {
                const int n = n_base + nt * 8 + fr;
                const int bidx = (cur * 128 + n) * APAD + kb + fk;
                uint32_t b_hi[2], b_lo[2];
                b_hi[0] = *(const uint32_t*)&sBhi[bidx];
                b_hi[1] = *(const uint32_t*)&sBhi[bidx + 8];
                b_lo[0] = *(const uint32_t*)&sBlo[bidx];
                b_lo[1] = *(const uint32_t*)&sBlo[bidx + 8];
#pragma unroll
                for (int mt = 0; mt < 4; mt++) {
                    mma_bf16(acc[mt][nt], a_hi[mt], b_hi);
                    mma_bf16(acc[mt][nt], a_hi[mt], b_lo);
                    mma_bf16(acc[mt][nt], a_lo[mt], b_hi);
                }
            }
        }
        __syncthreads();     // done reading cur before it is refilled at c+2
    }

    // epilogue: c0,c1 -> row fr; c2,c3 -> row fr+8
#pragma unroll
    for (int mt = 0; mt < 4; mt++)
#pragma unroll
        for (int nt = 0; nt < 4; nt++) {
            const int col0 = n0 + n_base + nt * 8 + fk;
#pragma unroll
            for (int half = 0; half < 2; half++) {
                const int row = m0 + m_base + mt * 16 + fr + half * 8;
                float v0 = acc[mt][nt][half * 2];
                float v1 = acc[mt][nt][half * 2 + 1];
                if (EPI == 1) {
                    const int nn = row >> 8, mm = row & 255;
                    v0 += g_hi[nn * H_DIM + col0]     + g_hj[mm * H_DIM + col0]     + bias[col0];
                    v1 += g_hi[nn * H_DIM + col0 + 1] + g_hj[mm * H_DIM + col0 + 1] + bias[col0 + 1];
                    v0 = (v0 >= 0.f) ? v0 : SLOPE * v0;
                    v1 = (v1 >= 0.f) ? v1 : SLOPE * v1;
                    __nv_bfloat16 h0, l0, h1, l1;
                    split_bf16(v0, h0, l0);
                    split_bf16(v1, h1, l1);
                    const size_t o = (size_t)row * H_DIM + col0;
                    *(__nv_bfloat162*)(g_hb_hi + o) = __nv_bfloat162(h0, h1);
                    *(__nv_bfloat162*)(g_hb_lo + o) = __nv_bfloat162(l0, l1);
                } else {
                    v0 += g_bias2[col0];
                    v1 += g_bias2[col0 + 1];
                    if (blockIdx.x < 8) {
                        *(float2*)(out_feat + (size_t)row * O_DIM + col0) = make_float2(v0, v1);
                    } else {
                        const int j0 = col0 - 1024;   // even
                        if (j0 < R_DIM)           out_rel[(size_t)row * R_DIM + j0] = v0;
                        if (j0 + 1 < R_DIM)       out_rel[(size_t)row * R_DIM + j0 + 1] = v1;
                        else if (j0 + 1 == R_DIM) g_conf[row] = v1;
                    }
                }
            }
        }
}

// ---------------- hi/hj: K-split fp32 GEMM (128 blocks) + reduce ---------------
__launch_bounds__(256)
__global__ void gemm_hij(const float* __restrict__ feats, const float* __restrict__ W1)
{
    const int which = blockIdx.z >> 2;
    const int kc = blockIdx.z & 3;
    __shared__ float As[8][132];
    __shared__ float Bs[8][128];
    const int tid = threadIdx.x;
    const int tx = tid & 15, ty = tid >> 4;
    const int m0 = blockIdx.y * 128, n0 = blockIdx.x * 128;
    float acc[8][8];
#pragma unroll
    for (int i = 0; i < 8; i++)
#pragma unroll
        for (int j = 0; j < 8; j++) acc[i][j] = 0.f;
    const int ar = tid >> 1, ak = (tid & 1) * 4;
    const int bk = tid >> 5, bc = (tid & 31) * 4;
    const float* Aptr = feats + (size_t)(m0 + ar) * 1024 + kc * 256 + ak;
    const float* Bptr = W1 + (size_t)(which * D_IN + kc * 256 + bk) * 1024 + n0 + bc;
    for (int k0 = 0; k0 < 256; k0 += 8) {
        float4 av = *(const float4*)(Aptr + k0);
        float4 bv = *(const float4*)(Bptr + (size_t)k0 * 1024);
        As[ak][ar] = av.x; As[ak + 1][ar] = av.y; As[ak + 2][ar] = av.z; As[ak + 3][ar] = av.w;
        *(float4*)(&Bs[bk][bc]) = bv;
        __syncthreads();
#pragma unroll
        for (int kk = 0; kk < 8; kk++) {
            float a[8], b[8];
#pragma unroll
            for (int i = 0; i < 8; i++) a[i] = As[kk][ty * 8 + i];
#pragma unroll
            for (int j = 0; j < 8; j++) b[j] = Bs[kk][tx * 8 + j];
#pragma unroll
            for (int i = 0; i < 8; i++)
#pragma unroll
                for (int j = 0; j < 8; j++) acc[i][j] += a[i] * b[j];
        }
        __syncthreads();
    }
    float* dst = g_part + (size_t)blockIdx.z * N_OBJ * H_DIM;
#pragma unroll
    for (int i = 0; i < 8; i++)
#pragma unroll
        for (int j = 0; j < 8; j++)
            dst[(size_t)(m0 + ty * 8 + i) * 1024 + n0 + tx * 8 + j] = acc[i][j];
}

__global__ void reduce_hij()
{
    const int idx = blockIdx.x * 256 + threadIdx.x;
    const int which = idx >> 18;
    const int base = idx & (N_OBJ * H_DIM - 1);
    const size_t stride = (size_t)N_OBJ * H_DIM;
    const float* p = g_part + (size_t)which * 4 * stride + base;
    const float s = p[0] + p[stride] + p[2 * stride] + p[3 * stride];
    if (which == 0) g_hi[base] = s;
    else            g_hj[base] = s;
}

// ---------------- converters ---------------------------------------------------
__global__ void convert_cemb(const float* __restrict__ in)
{
    const size_t i = ((size_t)blockIdx.x * 256 + threadIdx.x) * 4;
    if (i >= (size_t)NP * C_EMB) return;
    const float4 v4 = *(const float4*)(in + i);
    const float v[4] = { v4.x, v4.y, v4.z, v4.w };
    uint32_t hw[2], lw[2];
#pragma unroll
    for (int p = 0; p < 2; p++) {
        __nv_bfloat16 h0, l0, h1, l1;
        split_bf16(v[2 * p], h0, l0);
        split_bf16(v[2 * p + 1], h1, l1);
        hw[p] = (uint32_t)__bfloat16_as_ushort(h0) | ((uint32_t)__bfloat16_as_ushort(h1) << 16);
        lw[p] = (uint32_t)__bfloat16_as_ushort(l0) | ((uint32_t)__bfloat16_as_ushort(l1) << 16);
    }
    *(uint2*)((char*)g_c_hi + i * 2) = make_uint2(hw[0], hw[1]);
    *(uint2*)((char*)g_c_lo + i * 2) = make_uint2(lw[0], lw[1]);
}

// W1c^T split via 32x32 tiled transpose. grid (C_EMB/32, H_DIM/32), 256 thr.
__global__ void split_W1t(const float* __restrict__ W1)
{
    __shared__ float t[32][33];
    const int kb = blockIdx.x * 32;
    const int jb = blockIdx.y * 32;
    const int tx = threadIdx.x & 31, ty = threadIdx.x >> 5;
#pragma unroll
    for (int r = 0; r < 4; r++) {
        const int k = kb + ty + r * 8;
        t[ty + r * 8][tx] = W1[(size_t)(2 * D_IN + k) * H_DIM + jb + tx];
    }
    __syncthreads();
#pragma unroll
    for (int r = 0; r < 4; r++) {
        const int j = jb + ty + r * 8;
        const int k = kb + tx;
        __nv_bfloat16 h, l;
        split_bf16(t[tx][ty + r * 8], h, l);
        g_W1t_hi[(size_t)j * C_EMB + k] = h;
        g_W1t_lo[(size_t)j * C_EMB + k] = l;
    }
}

// wrelc = W2 @ W_rel [1024,51], wattc = W2 @ w_att [1024]  (one block per k-row)
__global__ void small_mats(const float* __restrict__ W2, const float* __restrict__ Wrel,
                           const float* __restrict__ watt)
{
    __shared__ float row[1024];
    const int i = blockIdx.x, tid = threadIdx.x;
    for (int o = tid; o < 1024; o += 256) row[o] = W2[(size_t)i * O_DIM + o];
    __syncthreads();
    if (tid < R_DIM) {
        float s = 0.f;
        for (int o = 0; o < 1024; o++) s += row[o] * Wrel[(size_t)o * R_DIM + tid];
        g_wrelc[i * R_DIM + tid] = s;
    } else if (tid == R_DIM) {
        float s = 0.f;
        for (int o = 0; o < 1024; o++) s += row[o] * watt[o];
        g_wattc[i] = s;
    }
}

// (scale.W2)^T split via 32x32 tiled transpose (cols 0..1023)
__global__ void build_W2ts(const float* __restrict__ W2)
{
    __shared__ float t[32][33];
    const int kb = blockIdx.x * 32;
    const int jb = blockIdx.y * 32;
    const int tx = threadIdx.x & 31, ty = threadIdx.x >> 5;
#pragma unroll
    for (int r = 0; r < 4; r++) {
        const int k = kb + ty + r * 8;
        t[ty + r * 8][tx] = W2[(size_t)k * O_DIM + jb + tx];
    }
    __syncthreads();
#pragma unroll
    for (int r = 0; r < 4; r++) {
        const int j = jb + ty + r * 8;
        const int k = kb + tx;
        __nv_bfloat16 h, l;
        split_bf16(g_scale[k] * t[tx][ty + r * 8], h, l);
        g_W2t_hi[(size_t)j * H_DIM + k] = h;
        g_W2t_lo[(size_t)j * H_DIM + k] = l;
    }
}

// extra B^T columns 1024..1151: rel (scale.wrelc), conf (scale.wattc), zero pad
__global__ void build_Bextra()
{
    const int j = 1024 + blockIdx.x;
    const int k = blockIdx.y * 256 + threadIdx.x;
    const int j0 = j - 1024;
    float w = 0.f;
    if (j0 < R_DIM)       w = g_scale[k] * g_wrelc[k * R_DIM + j0];
    else if (j0 == R_DIM) w = g_scale[k] * g_wattc[k];
    __nv_bfloat16 h, l;
    split_bf16(w, h, l);
    g_W2t_hi[(size_t)j * H_DIM + k] = h;
    g_W2t_lo[(size_t)j * H_DIM + k] = l;
}

// bias2[j<1024] = b2[j] + sum_k shift[k] * W2[k][j]
__global__ void build_bias2(const float* __restrict__ W2, const float* __restrict__ b2)
{
    const int j = blockIdx.x * 256 + threadIdx.x;
    float s = b2[j];
#pragma unroll 4
    for (int k = 0; k < H_DIM; k++)
        s += g_shift[k] * W2[(size_t)k * O_DIM + j];
    g_bias2[j] = s;
}

// bias2[1024+j0]: rel -> bias2[:1024]@Wrel + brel ; conf -> bias2.watt + batt ; 0 pad
__global__ void build_biasX(const float* __restrict__ Wrel, const float* __restrict__ brel,
                            const float* __restrict__ watt, const float* __restrict__ batt)
{
    __shared__ float red[256];
    const int j0 = blockIdx.x, tid = threadIdx.x;
    float a = 0.f;
    if (j0 < R_DIM) {
        for (int o = tid; o < 1024; o += 256) a += g_bias2[o] * Wrel[(size_t)o * R_DIM + j0];
    } else if (j0 == R_DIM) {
        for (int o = tid; o < 1024; o += 256) a += g_bias2[o] * watt[o];
    }
    red[tid] = a;
    __syncthreads();
    for (int o = 128; o; o >>= 1) {
        if (tid < o) red[tid] += red[tid + o];
        __syncthreads();
    }
    if (tid == 0) {
        float b = 0.f;
        if (j0 < R_DIM)       b = red[0] + brel[j0];
        else if (j0 == R_DIM) b = red[0] + batt[0];
        g_bias2[1024 + j0] = b;
    }
}

// ---------------- BN stats from split planes (deterministic) -------------------
__global__ void stats_planes()
{
    const int cp = blockIdx.x * 256 + threadIdx.x;
    const int rb = blockIdx.y;
    const int c0 = cp * 2;
    float s0 = 0.f, s1 = 0.f, q0 = 0.f, q1 = 0.f;
#pragma unroll 4
    for (int r = 0; r < 256; r++) {
        const size_t o = (size_t)(rb * 256 + r) * H_DIM + c0;
        const __nv_bfloat162 h2 = *(const __nv_bfloat162*)(g_hb_hi + o);
        const __nv_bfloat162 l2 = *(const __nv_bfloat162*)(g_hb_lo + o);
        const float v0 = __bfloat162float(h2.x) + __bfloat162float(l2.x);
        const float v1 = __bfloat162float(h2.y) + __bfloat162float(l2.y);
        s0 += v0; q0 += v0 * v0;
        s1 += v1; q1 += v1 * v1;
    }
    g_ps[rb * H_DIM + c0] = s0; g_ps[rb * H_DIM + c0 + 1] = s1;
    g_pq[rb * H_DIM + c0] = q0; g_pq[rb * H_DIM + c0 + 1] = q1;
}

__global__ void finalize_bn(const float* __restrict__ gamma, const float* __restrict__ beta)
{
    const int c = blockIdx.x * 256 + threadIdx.x;
    float s = 0.f, q = 0.f;
#pragma unroll
    for (int i = 0; i < RB_STATS; i++) { s += g_ps[i * H_DIM + c]; q += g_pq[i * H_DIM + c]; }
    const float inv = 1.0f / (float)NP;
    const float mean = s * inv;
    const float var = q * inv - mean * mean;
    const float sc = gamma[c] * rsqrtf(var + BN_EPS);
    g_scale[c] = sc;
    g_shift[c] = beta[c] - mean * sc;
}

// ---------------- softmax + weighted aggregation -------------------------------
__global__ void attn_agg(const float* __restrict__ feat, float* __restrict__ enhanced)
{
    __shared__ float conf[N_OBJ];
    __shared__ float red[256];
    const int n = blockIdx.x, tid = threadIdx.x;
    const int c0 = blockIdx.y * 256;
    const float v = g_conf[n * N_OBJ + tid];
    red[tid] = v;
    __syncthreads();
    for (int o = 128; o; o >>= 1) {
        if (tid < o) red[tid] = fmaxf(red[tid], red[tid + o]);
        __syncthreads();
    }
    const float mx = red[0];
    __syncthreads();
    const float e = expf(v - mx);
    red[tid] = e;
    __syncthreads();
    for (int o = 128; o; o >>= 1) {
        if (tid < o) red[tid] += red[tid + o];
        __syncthreads();
    }
    const float p = e / red[0];
    __syncthreads();
    conf[tid] = p;
    __syncthreads();

    float acc = 0.f;
    const float* base = feat + (size_t)n * N_OBJ * O_DIM + c0 + tid;
#pragma unroll 4
    for (int m = 0; m < N_OBJ; m++)
        acc += conf[m] * base[(size_t)m * O_DIM];
    enhanced[(size_t)n * O_DIM + c0 + tid] = acc;
}

// ---------------- launcher ------------------------------------------------------
// NOTE: every kernel argument below is a d_in/d_out pointer. Device scratch is
// reached only through device-code symbol references.
extern "C" void kernel_launch(void* const* d_in, const int* in_sizes, int n_in,
                              void* d_out, int out_size)
{
    const float* feats = (const float*)d_in[0];
    const float* cemb  = (const float*)d_in[1];
    const float* W1    = (const float*)d_in[2];
    const float* b1    = (const float*)d_in[3];
    const float* gamma = (const float*)d_in[4];
    const float* beta  = (const float*)d_in[5];
    const float* W2    = (const float*)d_in[6];
    const float* b2    = (const float*)d_in[7];
    const float* watt  = (const float*)d_in[8];
    const float* batt  = (const float*)d_in[9];
    const float* Wrel  = (const float*)d_in[10];
    const float* brel  = (const float*)d_in[11];

    float* out      = (float*)d_out;
    float* feat     = out;
    float* enhanced = out + (size_t)NP * O_DIM;
    float* relation = enhanced + (size_t)N_OBJ * O_DIM;

    // TK=32 path needs dynamic-smem opt-in (80KB). Checked every call
    // (deterministic); fall back to TK=16 @ 48KB (no opt-in needed) on failure.
    const int SMEM32 = 4 * 2 * 128 * 40 * 2;   // 81920
    const int SMEM16 = 4 * 2 * 128 * 24 * 2;   // 49152
    cudaError_t ea = cudaFuncSetAttribute(mma_gemm<1, 32>,
        cudaFuncAttributeMaxDynamicSharedMemorySize, SMEM32);
    cudaError_t eb = cudaFuncSetAttribute(mma_gemm<0, 32>,
        cudaFuncAttributeMaxDynamicSharedMemorySize, SMEM32);
    const bool use32 = (ea == cudaSuccess) && (eb == cudaSuccess);

    // converters + small mats (independent of GEMMs)
    convert_cemb<<<(int)(((size_t)NP * C_EMB / 4 + 255) / 256), 256>>>(cemb);
    split_W1t<<<dim3(C_EMB / 32, H_DIM / 32), 256>>>(W1);
    small_mats<<<H_DIM, 256>>>(W2, Wrel, watt);

    // hi/hj: K-split GEMM + deterministic reduce
    gemm_hij<<<dim3(8, 2, 8), 256>>>(feats, W1);
    reduce_hij<<<2 * N_OBJ * H_DIM / 256, 256>>>();

    // GEMM1 (HMMA): h = leakyrelu(cemb @ W1c + hi + hj + b1) -> split planes
    if (use32) mma_gemm<1, 32><<<dim3(8, 512), 256, SMEM32>>>(b1, nullptr, nullptr);
    else       mma_gemm<1, 16><<<dim3(8, 512), 256, SMEM16>>>(b1, nullptr, nullptr);

    // BN stats + fold into combined B / bias
    stats_planes<<<dim3(2, RB_STATS), 256>>>();
    finalize_bn<<<4, 256>>>(gamma, beta);
    build_W2ts<<<dim3(H_DIM / 32, O_DIM / 32), 256>>>(W2);
    build_Bextra<<<dim3(128, 4), 256>>>();
    build_bias2<<<O_DIM / 256, 256>>>(W2, b2);
    build_biasX<<<128, 256>>>(Wrel, brel, watt, batt);

    // GEMM2 (HMMA): [feat | relation | conf] = h @ Bcomb + bias2
    if (use32) mma_gemm<0, 32><<<dim3(9, 512), 256, SMEM32>>>(nullptr, feat, relation);
    else       mma_gemm<0, 16><<<dim3(9, 512), 256, SMEM16>>>(nullptr, feat, relation);

    // attention softmax + aggregation (logits from GEMM2)
    attn_agg<<<dim3(N_OBJ, 4), 256>>>(feat, enhanced);
}

// round 16
// speedup vs baseline: 1.2709x; 1.0188x over previous
#include <cuda_runtime.h>
#include <cuda_bf16.h>
#include <cstdint>
#include <math.h>

#define N_OBJ 256
#define D_IN  1024
#define C_EMB 256
#define H_DIM 1024
#define O_DIM 1024
#define R_DIM 51
#define NP    (N_OBJ * N_OBJ)   /* 65536 edge rows */
#define BN_EPS 1e-5f
#define SLOPE  0.01f
#define MBLK  512                /* GEMM1 m-blocks = stats partials */
#define N2TOT 1152               /* 1024 feat + 51 rel + 1 conf + 76 pad */

// ---------------- scratch (static device globals; no allocation) ---------------
// RULE (root cause of rounds 2-8): these symbols are ONLY referenced inside
// device code. NEVER passed as kernel arguments from kernel_launch (host code
// would pass the host shadow address; ATS on GB300 makes it read zeros).
__device__ __align__(128) __nv_bfloat16 g_c_hi[(size_t)NP * C_EMB];   // cemb split
__device__ __align__(128) __nv_bfloat16 g_c_lo[(size_t)NP * C_EMB];
__device__ __align__(128) __nv_bfloat16 g_W1t_hi[H_DIM * C_EMB];      // W1c^T split [j][k]
__device__ __align__(128) __nv_bfloat16 g_W1t_lo[H_DIM * C_EMB];
__device__ __align__(128) __nv_bfloat16 g_hb_hi[(size_t)NP * H_DIM];  // h split (pre-BN)
__device__ __align__(128) __nv_bfloat16 g_hb_lo[(size_t)NP * H_DIM];
__device__ __align__(128) __nv_bfloat16 g_W2t_hi[(size_t)N2TOT * H_DIM]; // combined B^T split
__device__ __align__(128) __nv_bfloat16 g_W2t_lo[(size_t)N2TOT * H_DIM];
__device__ float g_hi[N_OBJ * H_DIM];
__device__ float g_hj[N_OBJ * H_DIM];
__device__ float g_part[8 * N_OBJ * H_DIM];   // K-split partials for hi/hj
__device__ float g_ps[MBLK * H_DIM];          // fused BN partial sums (per m-block)
__device__ float g_pq[MBLK * H_DIM];          // fused BN partial sumsq
__device__ float g_scale[H_DIM];
__device__ float g_shift[H_DIM];
__device__ float g_bias2[N2TOT];              // [b2+shift.W2 | rel bias | conf bias | 0]
__device__ float g_wrelc[H_DIM * R_DIM];      // W2 @ W_rel
__device__ float g_wattc[H_DIM];              // W2 @ w_att
__device__ float g_conf[NP];                  // attention logits

__device__ __forceinline__ void mma_bf16(float* c, const uint32_t* a, const uint32_t* b) {
    asm volatile("mma.sync.aligned.m16n8k16.row.col.f32.bf16.bf16.f32 "
                 "{%0,%1,%2,%3}, {%4,%5,%6,%7}, {%8,%9}, {%0,%1,%2,%3};"
                 : "+f"(c[0]), "+f"(c[1]), "+f"(c[2]), "+f"(c[3])
                 : "r"(a[0]), "r"(a[1]), "r"(a[2]), "r"(a[3]), "r"(b[0]), "r"(b[1]));
}
__device__ __forceinline__ void split_bf16(float v, __nv_bfloat16& h, __nv_bfloat16& l) {
    h = __float2bfloat16_rn(v);
    l = __float2bfloat16_rn(v - __bfloat162float(h));
}
__device__ __forceinline__ uint32_t smem_u32(const void* p) {
    uint32_t a;
    asm("{ .reg .u64 t; cvta.to.shared.u64 t, %1; cvt.u32.u64 %0, t; }" : "=r"(a) : "l"(p));
    return a;
}
__device__ __forceinline__ void cp16(uint32_t s, const void* g) {
    asm volatile("cp.async.cg.shared.global [%0], [%1], 16;" :: "r"(s), "l"(g));
}
#define CP_COMMIT() asm volatile("cp.async.commit_group;" ::: "memory")
#define CP_WAIT0()  asm volatile("cp.async.wait_group 0;" ::: "memory")

// ---------------- HMMA bf16x3 GEMM (cp.async; 2 CTAs/SM; TKP-templated) --------
// EPI 1: h = leakyrelu(cemb @ W1c + g_hi[nn]+g_hj[mm]+bias) -> split planes
//        + FUSED per-column BN partial sums/sumsq -> g_ps/g_pq[blockIdx.y]  K=256
// EPI 0: [feat | rel | conf] = h @ Bcomb + g_bias2                         K=1024
template<int EPI, int TKP>
__global__ __launch_bounds__(256, 2)
void mma_gemm(const float* __restrict__ bias,
              float* __restrict__ out_feat,
              float* __restrict__ out_rel)
{
    constexpr int APAD = TKP + 8;
    constexpr int PLANE = 2 * 128 * APAD;      // elements per plane (2 stages)
    extern __shared__ __align__(16) __nv_bfloat16 dsm[];
    __nv_bfloat16* const sAhi = dsm;
    __nv_bfloat16* const sAlo = dsm + PLANE;
    __nv_bfloat16* const sBhi = dsm + 2 * PLANE;
    __nv_bfloat16* const sBlo = dsm + 3 * PLANE;

    const __nv_bfloat16* __restrict__ Ahi = (EPI == 1) ? g_c_hi : g_hb_hi;
    const __nv_bfloat16* __restrict__ Alo = (EPI == 1) ? g_c_lo : g_hb_lo;
    const __nv_bfloat16* __restrict__ Bhi = (EPI == 1) ? g_W1t_hi : g_W2t_hi;
    const __nv_bfloat16* __restrict__ Blo = (EPI == 1) ? g_W1t_lo : g_W2t_lo;
    constexpr int K = (EPI == 1) ? C_EMB : H_DIM;
    constexpr int NC = K / TKP;
    constexpr int GPP = TKP / 8;               // 16B granules per row per plane

    const int tid = threadIdx.x;
    const int lane = tid & 31, wid = tid >> 5;
    const int m0 = blockIdx.y * 128, n0 = blockIdx.x * 128;

    const int m_base = (wid >> 2) * 64;
    const int n_base = (wid & 3) * 32;
    const int fr = lane >> 2;             // fragment row 0..7
    const int fk = (lane & 3) * 2;        // fragment k 0,2,4,6

    // cp.async loader for one chunk
    auto load_chunk = [&](int c, int s) {
#pragma unroll
        for (int it = 0; it < TKP / 16; it++) {
            const int g = tid + it * 256;
            const int row = g / GPP;
            const int c16 = g % GPP;
            const size_t ka = (size_t)(m0 + row) * K + c * TKP + c16 * 8;
            const size_t kb = (size_t)(n0 + row) * K + c * TKP + c16 * 8;
            const uint32_t so = (uint32_t)(((s * 128 + row) * APAD + c16 * 8) * 2);
            cp16(smem_u32(sAhi) + so, Ahi + ka);
            cp16(smem_u32(sAlo) + so, Alo + ka);
            cp16(smem_u32(sBhi) + so, Bhi + kb);
            cp16(smem_u32(sBlo) + so, Blo + kb);
        }
    };

    float acc[4][4][4];
#pragma unroll
    for (int i = 0; i < 4; i++)
#pragma unroll
        for (int j = 0; j < 4; j++)
#pragma unroll
            for (int r = 0; r < 4; r++) acc[i][j][r] = 0.f;

    load_chunk(0, 0);
    CP_COMMIT();

    for (int c = 0; c < NC; c++) {
        const int cur = c & 1, nxt = cur ^ 1;
        CP_WAIT0();          // drain chunk c (sole pending group)
        __syncthreads();     // all threads see buffer cur; nxt free to overwrite
        if (c + 1 < NC) load_chunk(c + 1, nxt);
        CP_COMMIT();         // overlaps with compute below

#pragma unroll
        for (int ks = 0; ks < TKP / 16; ks++) {
            const int kb = ks * 16;
            uint32_t a_hi[4][4], a_lo[4][4];
#pragma unroll
            for (int mt = 0; mt < 4; mt++) {
                const int r0 = m_base + mt * 16 + fr;
                const int base0 = (cur * 128 + r0) * APAD + kb + fk;
                a_hi[mt][0] = *(const uint32_t*)&sAhi[base0];
                a_hi[mt][1] = *(const uint32_t*)&sAhi[base0 + 8 * APAD];
                a_hi[mt][2] = *(const uint32_t*)&sAhi[base0 + 8];
                a_hi[mt][3] = *(const uint32_t*)&sAhi[base0 + 8 * APAD + 8];
                a_lo[mt][0] = *(const uint32_t*)&sAlo[base0];
                a_lo[mt][1] = *(const uint32_t*)&sAlo[base0 + 8 * APAD];
                a_lo[mt][2] = *(const uint32_t*)&sAlo[base0 + 8];
                a_lo[mt][3] = *(const uint32_t*)&sAlo[base0 + 8 * APAD + 8];
            }
#pragma unroll
            for (int nt = 0; nt < 4; nt++) {
                const int n = n_base + nt * 8 + fr;
                const int bidx = (cur * 128 + n) * APAD + kb + fk;
                uint32_t b_hi[2], b_lo[2];
                b_hi[0] = *(const uint32_t*)&sBhi[bidx];
                b_hi[1] = *(const uint32_t*)&sBhi[bidx + 8];
                b_lo[0] = *(const uint32_t*)&sBlo[bidx];
                b_lo[1] = *(const uint32_t*)&sBlo[bidx + 8];
#pragma unroll
                for (int mt = 0; mt < 4; mt++) {
                    mma_bf16(acc[mt][nt], a_hi[mt], b_hi);
                    mma_bf16(acc[mt][nt], a_hi[mt], b_lo);
                    mma_bf16(acc[mt][nt], a_lo[mt], b_hi);
                }
            }
        }
        __syncthreads();     // done reading cur before it is refilled at c+2
    }
    // NOTE: final loop iteration's __syncthreads means all warps are done with
    // smem -> dsm is reusable as the stats staging buffer below.

    // epilogue: c0,c1 -> row fr; c2,c3 -> row fr+8
#pragma unroll
    for (int nt = 0; nt < 4; nt++) {
        const int col0 = n0 + n_base + nt * 8 + fk;
        float s0 = 0.f, s1 = 0.f, q0 = 0.f, q1 = 0.f;
#pragma unroll
        for (int mt = 0; mt < 4; mt++) {
#pragma unroll
            for (int half = 0; half < 2; half++) {
                const int row = m0 + m_base + mt * 16 + fr + half * 8;
                float v0 = acc[mt][nt][half * 2];
                float v1 = acc[mt][nt][half * 2 + 1];
                if (EPI == 1) {
                    const int nn = row >> 8, mm = row & 255;
                    v0 += g_hi[nn * H_DIM + col0]     + g_hj[mm * H_DIM + col0]     + bias[col0];
                    v1 += g_hi[nn * H_DIM + col0 + 1] + g_hj[mm * H_DIM + col0 + 1] + bias[col0 + 1];
                    v0 = (v0 >= 0.f) ? v0 : SLOPE * v0;
                    v1 = (v1 >= 0.f) ? v1 : SLOPE * v1;
                    s0 += v0; q0 += v0 * v0;
                    s1 += v1; q1 += v1 * v1;
                    __nv_bfloat16 h0, l0, h1, l1;
                    split_bf16(v0, h0, l0);
                    split_bf16(v1, h1, l1);
                    const size_t o = (size_t)row * H_DIM + col0;
                    *(__nv_bfloat162*)(g_hb_hi + o) = __nv_bfloat162(h0, h1);
                    *(__nv_bfloat162*)(g_hb_lo + o) = __nv_bfloat162(l0, l1);
                } else {
                    v0 += g_bias2[col0];
                    v1 += g_bias2[col0 + 1];
                    if (blockIdx.x < 8) {
                        *(float2*)(out_feat + (size_t)row * O_DIM + col0) = make_float2(v0, v1);
                    } else {
                        const int j0 = col0 - 1024;   // even
                        if (j0 < R_DIM)           out_rel[(size_t)row * R_DIM + j0] = v0;
                        if (j0 + 1 < R_DIM)       out_rel[(size_t)row * R_DIM + j0 + 1] = v1;
                        else if (j0 + 1 == R_DIM) g_conf[row] = v1;
                    }
                }
            }
        }
        if (EPI == 1) {
            // reduce over the 8 fr-lanes sharing this column pair
#pragma unroll
            for (int o = 16; o >= 4; o >>= 1) {
                s0 += __shfl_xor_sync(0xFFFFFFFFu, s0, o);
                s1 += __shfl_xor_sync(0xFFFFFFFFu, s1, o);
                q0 += __shfl_xor_sync(0xFFFFFFFFu, q0, o);
                q1 += __shfl_xor_sync(0xFFFFFFFFu, q1, o);
            }
            if (lane < 4) {
                float* sred = (float*)dsm;   // [wid][nt][lq][2], sq at +256
                const int base = ((wid * 4 + nt) * 4 + lane) * 2;
                sred[base]     = s0;
                sred[base + 1] = s1;
                sred[256 + base]     = q0;
                sred[256 + base + 1] = q1;
            }
        }
    }
    if (EPI == 1) {
        __syncthreads();
        if (tid < 128) {   // one thread per block column
            const float* sred = (const float*)dsm;
            const int g = tid >> 5, rem = tid & 31;
            const int nt = rem >> 3, lq = (rem & 7) >> 1, c = rem & 1;
            const int i0 = ((g * 4 + nt) * 4 + lq) * 2 + c;        // m_base 0 warp
            const int i1 = (((g + 4) * 4 + nt) * 4 + lq) * 2 + c;  // m_base 64 warp
            g_ps[(size_t)blockIdx.y * H_DIM + n0 + rem + g * 32] = sred[i0] + sred[i1];
            g_pq[(size_t)blockIdx.y * H_DIM + n0 + rem + g * 32] = sred[256 + i0] + sred[256 + i1];
        }
    }
}

// ---------------- hi/hj: K-split fp32 GEMM (128 blocks) + reduce ---------------
__launch_bounds__(256)
__global__ void gemm_hij(const float* __restrict__ feats, const float* __restrict__ W1)
{
    const int which = blockIdx.z >> 2;
    const int kc = blockIdx.z & 3;
    __shared__ float As[8][132];
    __shared__ float Bs[8][128];
    const int tid = threadIdx.x;
    const int tx = tid & 15, ty = tid >> 4;
    const int m0 = blockIdx.y * 128, n0 = blockIdx.x * 128;
    float acc[8][8];
#pragma unroll
    for (int i = 0; i < 8; i++)
#pragma unroll
        for (int j = 0; j < 8; j++) acc[i][j] = 0.f;
    const int ar = tid >> 1, ak = (tid & 1) * 4;
    const int bk = tid >> 5, bc = (tid & 31) * 4;
    const float* Aptr = feats + (size_t)(m0 + ar) * 1024 + kc * 256 + ak;
    const float* Bptr = W1 + (size_t)(which * D_IN + kc * 256 + bk) * 1024 + n0 + bc;
    for (int k0 = 0; k0 < 256; k0 += 8) {
        float4 av = *(const float4*)(Aptr + k0);
        float4 bv = *(const float4*)(Bptr + (size_t)k0 * 1024);
        As[ak][ar] = av.x; As[ak + 1][ar] = av.y; As[ak + 2][ar] = av.z; As[ak + 3][ar] = av.w;
        *(float4*)(&Bs[bk][bc]) = bv;
        __syncthreads();
#pragma unroll
        for (int kk = 0; kk < 8; kk++) {
            float a[8], b[8];
#pragma unroll
            for (int i = 0; i < 8; i++) a[i] = As[kk][ty * 8 + i];
#pragma unroll
            for (int j = 0; j < 8; j++) b[j] = Bs[kk][tx * 8 + j];
#pragma unroll
            for (int i = 0; i < 8; i++)
#pragma unroll
                for (int j = 0; j < 8; j++) acc[i][j] += a[i] * b[j];
        }
        __syncthreads();
    }
    float* dst = g_part + (size_t)blockIdx.z * N_OBJ * H_DIM;
#pragma unroll
    for (int i = 0; i < 8; i++)
#pragma unroll
        for (int j = 0; j < 8; j++)
            dst[(size_t)(m0 + ty * 8 + i) * 1024 + n0 + tx * 8 + j] = acc[i][j];
}

__global__ void reduce_hij()
{
    const int idx = blockIdx.x * 256 + threadIdx.x;
    const int which = idx >> 18;
    const int base = idx & (N_OBJ * H_DIM - 1);
    const size_t stride = (size_t)N_OBJ * H_DIM;
    const float* p = g_part + (size_t)which * 4 * stride + base;
    const float s = p[0] + p[stride] + p[2 * stride] + p[3 * stride];
    if (which == 0) g_hi[base] = s;
    else            g_hj[base] = s;
}

// ---------------- converters ---------------------------------------------------
__global__ void convert_cemb(const float* __restrict__ in)
{
    const size_t i = ((size_t)blockIdx.x * 256 + threadIdx.x) * 4;
    if (i >= (size_t)NP * C_EMB) return;
    const float4 v4 = *(const float4*)(in + i);
    const float v[4] = { v4.x, v4.y, v4.z, v4.w };
    uint32_t hw[2], lw[2];
#pragma unroll
    for (int p = 0; p < 2; p++) {
        __nv_bfloat16 h0, l0, h1, l1;
        split_bf16(v[2 * p], h0, l0);
        split_bf16(v[2 * p + 1], h1, l1);
        hw[p] = (uint32_t)__bfloat16_as_ushort(h0) | ((uint32_t)__bfloat16_as_ushort(h1) << 16);
        lw[p] = (uint32_t)__bfloat16_as_ushort(l0) | ((uint32_t)__bfloat16_as_ushort(l1) << 16);
    }
    *(uint2*)((char*)g_c_hi + i * 2) = make_uint2(hw[0], hw[1]);
    *(uint2*)((char*)g_c_lo + i * 2) = make_uint2(lw[0], lw[1]);
}

// W1c^T split via 32x32 tiled transpose. grid (C_EMB/32, H_DIM/32), 256 thr.
__global__ void split_W1t(const float* __restrict__ W1)
{
    __shared__ float t[32][33];
    const int kb = blockIdx.x * 32;
    const int jb = blockIdx.y * 32;
    const int tx = threadIdx.x & 31, ty = threadIdx.x >> 5;
#pragma unroll
    for (int r = 0; r < 4; r++) {
        const int k = kb + ty + r * 8;
        t[ty + r * 8][tx] = W1[(size_t)(2 * D_IN + k) * H_DIM + jb + tx];
    }
    __syncthreads();
#pragma unroll
    for (int r = 0; r < 4; r++) {
        const int j = jb + ty + r * 8;
        const int k = kb + tx;
        __nv_bfloat16 h, l;
        split_bf16(t[tx][ty + r * 8], h, l);
        g_W1t_hi[(size_t)j * C_EMB + k] = h;
        g_W1t_lo[(size_t)j * C_EMB + k] = l;
    }
}

// wrelc = W2 @ W_rel [1024,51], wattc = W2 @ w_att [1024]  (one block per k-row)
__global__ void small_mats(const float* __restrict__ W2, const float* __restrict__ Wrel,
                           const float* __restrict__ watt)
{
    __shared__ float row[1024];
    const int i = blockIdx.x, tid = threadIdx.x;
    for (int o = tid; o < 1024; o += 256) row[o] = W2[(size_t)i * O_DIM + o];
    __syncthreads();
    if (tid < R_DIM) {
        float s = 0.f;
        for (int o = 0; o < 1024; o++) s += row[o] * Wrel[(size_t)o * R_DIM + tid];
        g_wrelc[i * R_DIM + tid] = s;
    } else if (tid == R_DIM) {
        float s = 0.f;
        for (int o = 0; o < 1024; o++) s += row[o] * watt[o];
        g_wattc[i] = s;
    }
}

// (scale.W2)^T split via 32x32 tiled transpose (cols 0..1023)
__global__ void build_W2ts(const float* __restrict__ W2)
{
    __shared__ float t[32][33];
    const int kb = blockIdx.x * 32;
    const int jb = blockIdx.y * 32;
    const int tx = threadIdx.x & 31, ty = threadIdx.x >> 5;
#pragma unroll
    for (int r = 0; r < 4; r++) {
        const int k = kb + ty + r * 8;
        t[ty + r * 8][tx] = W2[(size_t)k * O_DIM + jb + tx];
    }
    __syncthreads();
#pragma unroll
    for (int r = 0; r < 4; r++) {
        const int j = jb + ty + r * 8;
        const int k = kb + tx;
        __nv_bfloat16 h, l;
        split_bf16(g_scale[k] * t[tx][ty + r * 8], h, l);
        g_W2t_hi[(size_t)j * H_DIM + k] = h;
        g_W2t_lo[(size_t)j * H_DIM + k] = l;
    }
}

// extra B^T columns 1024..1151: rel (scale.wrelc), conf (scale.wattc), zero pad
__global__ void build_Bextra()
{
    const int j = 1024 + blockIdx.x;
    const int k = blockIdx.y * 256 + threadIdx.x;
    const int j0 = j - 1024;
    float w = 0.f;
    if (j0 < R_DIM)       w = g_scale[k] * g_wrelc[k * R_DIM + j0];
    else if (j0 == R_DIM) w = g_scale[k] * g_wattc[k];
    __nv_bfloat16 h, l;
    split_bf16(w, h, l);
    g_W2t_hi[(size_t)j * H_DIM + k] = h;
    g_W2t_lo[(size_t)j * H_DIM + k] = l;
}

// bias2[j<1024] = b2[j] + sum_k shift[k] * W2[k][j]
__global__ void build_bias2(const float* __restrict__ W2, const float* __restrict__ b2)
{
    const int j = blockIdx.x * 256 + threadIdx.x;
    float s = b2[j];
#pragma unroll 4
    for (int k = 0; k < H_DIM; k++)
        s += g_shift[k] * W2[(size_t)k * O_DIM + j];
    g_bias2[j] = s;
}

// bias2[1024+j0]: rel -> bias2[:1024]@Wrel + brel ; conf -> bias2.watt + batt ; 0 pad
__global__ void build_biasX(const float* __restrict__ Wrel, const float* __restrict__ brel,
                            const float* __restrict__ watt, const float* __restrict__ batt)
{
    __shared__ float red[256];
    const int j0 = blockIdx.x, tid = threadIdx.x;
    float a = 0.f;
    if (j0 < R_DIM) {
        for (int o = tid; o < 1024; o += 256) a += g_bias2[o] * Wrel[(size_t)o * R_DIM + j0];
    } else if (j0 == R_DIM) {
        for (int o = tid; o < 1024; o += 256) a += g_bias2[o] * watt[o];
    }
    red[tid] = a;
    __syncthreads();
    for (int o = 128; o; o >>= 1) {
        if (tid < o) red[tid] += red[tid + o];
        __syncthreads();
    }
    if (tid == 0) {
        float b = 0.f;
        if (j0 < R_DIM)       b = red[0] + brel[j0];
        else if (j0 == R_DIM) b = red[0] + batt[0];
        g_bias2[1024 + j0] = b;
    }
}

// ---------------- BN finalize from fused per-m-block partials ------------------
__global__ void finalize_bn(const float* __restrict__ gamma, const float* __restrict__ beta)
{
    const int c = blockIdx.x * 256 + threadIdx.x;
    float s = 0.f, q = 0.f;
#pragma unroll 8
    for (int i = 0; i < MBLK; i++) { s += g_ps[i * H_DIM + c]; q += g_pq[i * H_DIM + c]; }
    const float inv = 1.0f / (float)NP;
    const float mean = s * inv;
    const float var = q * inv - mean * mean;
    const float sc = gamma[c] * rsqrtf(var + BN_EPS);
    g_scale[c] = sc;
    g_shift[c] = beta[c] - mean * sc;
}

// ---------------- softmax + weighted aggregation -------------------------------
__global__ void attn_agg(const float* __restrict__ feat, float* __restrict__ enhanced)
{
    __shared__ float conf[N_OBJ];
    __shared__ float red[256];
    const int n = blockIdx.x, tid = threadIdx.x;
    const int c0 = blockIdx.y * 256;
    const float v = g_conf[n * N_OBJ + tid];
    red[tid] = v;
    __syncthreads();
    for (int o = 128; o; o >>= 1) {
        if (tid < o) red[tid] = fmaxf(red[tid], red[tid + o]);
        __syncthreads();
    }
    const float mx = red[0];
    __syncthreads();
    const float e = expf(v - mx);
    red[tid] = e;
    __syncthreads();
    for (int o = 128; o; o >>= 1) {
        if (tid < o) red[tid] += red[tid + o];
        __syncthreads();
    }
    const float p = e / red[0];
    __syncthreads();
    conf[tid] = p;
    __syncthreads();

    float acc = 0.f;
    const float* base = feat + (size_t)n * N_OBJ * O_DIM + c0 + tid;
#pragma unroll 4
    for (int m = 0; m < N_OBJ; m++)
        acc += conf[m] * base[(size_t)m * O_DIM];
    enhanced[(size_t)n * O_DIM + c0 + tid] = acc;
}

// ---------------- launcher ------------------------------------------------------
// NOTE: every kernel argument below is a d_in/d_out pointer. Device scratch is
// reached only through device-code symbol references.
extern "C" void kernel_launch(void* const* d_in, const int* in_sizes, int n_in,
                              void* d_out, int out_size)
{
    const float* feats = (const float*)d_in[0];
    const float* cemb  = (const float*)d_in[1];
    const float* W1    = (const float*)d_in[2];
    const float* b1    = (const float*)d_in[3];
    const float* gamma = (const float*)d_in[4];
    const float* beta  = (const float*)d_in[5];
    const float* W2    = (const float*)d_in[6];
    const float* b2    = (const float*)d_in[7];
    const float* watt  = (const float*)d_in[8];
    const float* batt  = (const float*)d_in[9];
    const float* Wrel  = (const float*)d_in[10];
    const float* brel  = (const float*)d_in[11];

    float* out      = (float*)d_out;
    float* feat     = out;
    float* enhanced = out + (size_t)NP * O_DIM;
    float* relation = enhanced + (size_t)N_OBJ * O_DIM;

    // TK=32 path needs dynamic-smem opt-in (80KB). Checked every call
    // (deterministic); fall back to TK=16 @ 48KB (no opt-in needed) on failure.
    const int SMEM32 = 4 * 2 * 128 * 40 * 2;   // 81920
    const int SMEM16 = 4 * 2 * 128 * 24 * 2;   // 49152
    cudaError_t ea = cudaFuncSetAttribute(mma_gemm<1, 32>,
        cudaFuncAttributeMaxDynamicSharedMemorySize, SMEM32);
    cudaError_t eb = cudaFuncSetAttribute(mma_gemm<0, 32>,
        cudaFuncAttributeMaxDynamicSharedMemorySize, SMEM32);
    const bool use32 = (ea == cudaSuccess) && (eb == cudaSuccess);

    // converters + small mats (independent of GEMMs)
    convert_cemb<<<(int)(((size_t)NP * C_EMB / 4 + 255) / 256), 256>>>(cemb);
    split_W1t<<<dim3(C_EMB / 32, H_DIM / 32), 256>>>(W1);
    small_mats<<<H_DIM, 256>>>(W2, Wrel, watt);

    // hi/hj: K-split GEMM + deterministic reduce
    gemm_hij<<<dim3(8, 2, 8), 256>>>(feats, W1);
    reduce_hij<<<2 * N_OBJ * H_DIM / 256, 256>>>();

    // GEMM1 (HMMA): h = leakyrelu(...) -> split planes, BN stats fused in epilogue
    if (use32) mma_gemm<1, 32><<<dim3(8, 512), 256, SMEM32>>>(b1, nullptr, nullptr);
    else       mma_gemm<1, 16><<<dim3(8, 512), 256, SMEM16>>>(b1, nullptr, nullptr);

    // BN finalize + fold into combined B / bias (no separate stats pass)
    finalize_bn<<<4, 256>>>(gamma, beta);
    build_W2ts<<<dim3(H_DIM / 32, O_DIM / 32), 256>>>(W2);
    build_Bextra<<<dim3(128, 4), 256>>>();
    build_bias2<<<O_DIM / 256, 256>>>(W2, b2);
    build_biasX<<<128, 256>>>(Wrel, brel, watt, batt);

    // GEMM2 (HMMA): [feat | relation | conf] = h @ Bcomb + bias2
    if (use32) mma_gemm<0, 32><<<dim3(9, 512), 256, SMEM32>>>(nullptr, feat, relation);
    else       mma_gemm<0, 16><<<dim3(9, 512), 256, SMEM16>>>(nullptr, feat, relation);

    // attention softmax + aggregation (logits from GEMM2)
    attn_agg<<<dim3(N_OBJ, 4), 256>>>(feat, enhanced);
}

// round 17
// speedup vs baseline: 1.6765x; 1.3192x over previous
#include <cuda_runtime.h>
#include <cuda_bf16.h>
#include <cuda_fp16.h>
#include <cstdint>
#include <math.h>

#define N_OBJ 256
#define D_IN  1024
#define C_EMB 256
#define H_DIM 1024
#define O_DIM 1024
#define R_DIM 51
#define NP    (N_OBJ * N_OBJ)   /* 65536 edge rows */
#define BN_EPS 1e-5f
#define SLOPE  0.01f
#define MBLK  512                /* GEMM1 m-blocks = stats partials */
#define N2TOT 1152               /* 1024 feat + 51 rel + 1 conf + 76 pad */

// ---------------- scratch (static device globals; no allocation) ---------------
// RULE (root cause of rounds 2-8): these symbols are ONLY referenced inside
// device code. NEVER passed as kernel arguments from kernel_launch (host code
// would pass the host shadow address; ATS on GB300 makes it read zeros).
__device__ __align__(128) __half g_c[(size_t)NP * C_EMB];       // cemb fp16 (single)
__device__ __align__(128) __half g_W1t_hi[H_DIM * C_EMB];       // W1c^T fp16 split [j][k]
__device__ __align__(128) __half g_W1t_lo[H_DIM * C_EMB];
__device__ __align__(128) __half g_hb[(size_t)NP * H_DIM];      // h fp16 (single, pre-BN)
__device__ __align__(128) __half g_W2t_hi[(size_t)N2TOT * H_DIM]; // combined B^T fp16 split
__device__ __align__(128) __half g_W2t_lo[(size_t)N2TOT * H_DIM];
__device__ float g_hi[N_OBJ * H_DIM];
__device__ float g_hj[N_OBJ * H_DIM];
__device__ float g_part[8 * N_OBJ * H_DIM];   // K-split partials for hi/hj
__device__ float g_ps[MBLK * H_DIM];          // fused BN partial sums (per m-block)
__device__ float g_pq[MBLK * H_DIM];          // fused BN partial sumsq
__device__ float g_scale[H_DIM];
__device__ float g_shift[H_DIM];
__device__ float g_bias2[N2TOT];              // [b2+shift.W2 | rel bias | conf bias | 0]
__device__ float g_wrelc[H_DIM * R_DIM];      // W2 @ W_rel
__device__ float g_wattc[H_DIM];              // W2 @ w_att
__device__ float g_conf[NP];                  // attention logits

__device__ __forceinline__ void mma_fp16(float* c, const uint32_t* a, const uint32_t* b) {
    asm volatile("mma.sync.aligned.m16n8k16.row.col.f32.f16.f16.f32 "
                 "{%0,%1,%2,%3}, {%4,%5,%6,%7}, {%8,%9}, {%0,%1,%2,%3};"
                 : "+f"(c[0]), "+f"(c[1]), "+f"(c[2]), "+f"(c[3])
                 : "r"(a[0]), "r"(a[1]), "r"(a[2]), "r"(a[3]), "r"(b[0]), "r"(b[1]));
}
__device__ __forceinline__ void split_fp16(float v, __half& h, __half& l) {
    h = __float2half_rn(v);
    l = __float2half_rn(v - __half2float(h));
}
__device__ __forceinline__ uint32_t smem_u32(const void* p) {
    uint32_t a;
    asm("{ .reg .u64 t; cvta.to.shared.u64 t, %1; cvt.u32.u64 %0, t; }" : "=r"(a) : "l"(p));
    return a;
}
__device__ __forceinline__ void cp16(uint32_t s, const void* g) {
    asm volatile("cp.async.cg.shared.global [%0], [%1], 16;" :: "r"(s), "l"(g));
}
#define CP_COMMIT() asm volatile("cp.async.commit_group;" ::: "memory")
#define CP_WAIT0()  asm volatile("cp.async.wait_group 0;" ::: "memory")

// ---------------- HMMA fp16 GEMM: A single fp16, B split fp16x2 (2 products) ---
// EPI 1: h = leakyrelu(cemb @ W1c + g_hi[nn]+g_hj[mm]+bias) -> fp16 plane
//        + FUSED per-column BN partial sums/sumsq -> g_ps/g_pq[blockIdx.y]  K=256
// EPI 0: [feat | rel | conf] = h @ Bcomb + g_bias2                         K=1024
template<int EPI, int TKP>
__global__ __launch_bounds__(256, 2)
void mma_gemm(const float* __restrict__ bias,
              float* __restrict__ out_feat,
              float* __restrict__ out_rel)
{
    constexpr int APAD = TKP + 8;
    constexpr int PLANE = 2 * 128 * APAD;      // elements per plane (2 stages)
    extern __shared__ __align__(16) __half dsm[];
    __half* const sA   = dsm;
    __half* const sBhi = dsm + PLANE;
    __half* const sBlo = dsm + 2 * PLANE;

    const __half* __restrict__ A   = (EPI == 1) ? g_c : g_hb;
    const __half* __restrict__ Bhi = (EPI == 1) ? g_W1t_hi : g_W2t_hi;
    const __half* __restrict__ Blo = (EPI == 1) ? g_W1t_lo : g_W2t_lo;
    constexpr int K = (EPI == 1) ? C_EMB : H_DIM;
    constexpr int NC = K / TKP;
    constexpr int GPP = TKP / 8;               // 16B granules per row per plane

    const int tid = threadIdx.x;
    const int lane = tid & 31, wid = tid >> 5;
    const int m0 = blockIdx.y * 128, n0 = blockIdx.x * 128;

    const int m_base = (wid >> 2) * 64;
    const int n_base = (wid & 3) * 32;
    const int fr = lane >> 2;             // fragment row 0..7
    const int fk = (lane & 3) * 2;        // fragment k 0,2,4,6

    // cp.async loader for one chunk (3 planes)
    auto load_chunk = [&](int c, int s) {
#pragma unroll
        for (int it = 0; it < TKP / 16; it++) {
            const int g = tid + it * 256;
            const int row = g / GPP;
            const int c16 = g % GPP;
            const size_t ka = (size_t)(m0 + row) * K + c * TKP + c16 * 8;
            const size_t kb = (size_t)(n0 + row) * K + c * TKP + c16 * 8;
            const uint32_t so = (uint32_t)(((s * 128 + row) * APAD + c16 * 8) * 2);
            cp16(smem_u32(sA) + so,   A + ka);
            cp16(smem_u32(sBhi) + so, Bhi + kb);
            cp16(smem_u32(sBlo) + so, Blo + kb);
        }
    };

    float acc[4][4][4];
#pragma unroll
    for (int i = 0; i < 4; i++)
#pragma unroll
        for (int j = 0; j < 4; j++)
#pragma unroll
            for (int r = 0; r < 4; r++) acc[i][j][r] = 0.f;

    load_chunk(0, 0);
    CP_COMMIT();

    for (int c = 0; c < NC; c++) {
        const int cur = c & 1, nxt = cur ^ 1;
        CP_WAIT0();          // drain chunk c (sole pending group)
        __syncthreads();     // all threads see buffer cur; nxt free to overwrite
        if (c + 1 < NC) load_chunk(c + 1, nxt);
        CP_COMMIT();         // overlaps with compute below

#pragma unroll
        for (int ks = 0; ks < TKP / 16; ks++) {
            const int kb = ks * 16;
            uint32_t a[4][4];
#pragma unroll
            for (int mt = 0; mt < 4; mt++) {
                const int r0 = m_base + mt * 16 + fr;
                const int base0 = (cur * 128 + r0) * APAD + kb + fk;
                a[mt][0] = *(const uint32_t*)&sA[base0];
                a[mt][1] = *(const uint32_t*)&sA[base0 + 8 * APAD];
                a[mt][2] = *(const uint32_t*)&sA[base0 + 8];
                a[mt][3] = *(const uint32_t*)&sA[base0 + 8 * APAD + 8];
            }
#pragma unroll
            for (int nt = 0; nt < 4; nt++) {
                const int n = n_base + nt * 8 + fr;
                const int bidx = (cur * 128 + n) * APAD + kb + fk;
                uint32_t b_hi[2], b_lo[2];
                b_hi[0] = *(const uint32_t*)&sBhi[bidx];
                b_hi[1] = *(const uint32_t*)&sBhi[bidx + 8];
                b_lo[0] = *(const uint32_t*)&sBlo[bidx];
                b_lo[1] = *(const uint32_t*)&sBlo[bidx + 8];
#pragma unroll
                for (int mt = 0; mt < 4; mt++) {
                    mma_fp16(acc[mt][nt], a[mt], b_hi);
                    mma_fp16(acc[mt][nt], a[mt], b_lo);
                }
            }
        }
        __syncthreads();     // done reading cur before it is refilled at c+2
    }
    // NOTE: final loop iteration's __syncthreads means all warps are done with
    // smem -> dsm is reusable as the stats staging buffer below.

    // epilogue: c0,c1 -> row fr; c2,c3 -> row fr+8
#pragma unroll
    for (int nt = 0; nt < 4; nt++) {
        const int col0 = n0 + n_base + nt * 8 + fk;
        float s0 = 0.f, s1 = 0.f, q0 = 0.f, q1 = 0.f;
#pragma unroll
        for (int mt = 0; mt < 4; mt++) {
#pragma unroll
            for (int half = 0; half < 2; half++) {
                const int row = m0 + m_base + mt * 16 + fr + half * 8;
                float v0 = acc[mt][nt][half * 2];
                float v1 = acc[mt][nt][half * 2 + 1];
                if (EPI == 1) {
                    const int nn = row >> 8, mm = row & 255;
                    v0 += g_hi[nn * H_DIM + col0]     + g_hj[mm * H_DIM + col0]     + bias[col0];
                    v1 += g_hi[nn * H_DIM + col0 + 1] + g_hj[mm * H_DIM + col0 + 1] + bias[col0 + 1];
                    v0 = (v0 >= 0.f) ? v0 : SLOPE * v0;
                    v1 = (v1 >= 0.f) ? v1 : SLOPE * v1;
                    s0 += v0; q0 += v0 * v0;
                    s1 += v1; q1 += v1 * v1;
                    const size_t o = (size_t)row * H_DIM + col0;
                    *(__half2*)(g_hb + o) = __halves2half2(__float2half_rn(v0),
                                                           __float2half_rn(v1));
                } else {
                    v0 += g_bias2[col0];
                    v1 += g_bias2[col0 + 1];
                    if (blockIdx.x < 8) {
                        *(float2*)(out_feat + (size_t)row * O_DIM + col0) = make_float2(v0, v1);
                    } else {
                        const int j0 = col0 - 1024;   // even
                        if (j0 < R_DIM)           out_rel[(size_t)row * R_DIM + j0] = v0;
                        if (j0 + 1 < R_DIM)       out_rel[(size_t)row * R_DIM + j0 + 1] = v1;
                        else if (j0 + 1 == R_DIM) g_conf[row] = v1;
                    }
                }
            }
        }
        if (EPI == 1) {
            // reduce over the 8 fr-lanes sharing this column pair
#pragma unroll
            for (int o = 16; o >= 4; o >>= 1) {
                s0 += __shfl_xor_sync(0xFFFFFFFFu, s0, o);
                s1 += __shfl_xor_sync(0xFFFFFFFFu, s1, o);
                q0 += __shfl_xor_sync(0xFFFFFFFFu, q0, o);
                q1 += __shfl_xor_sync(0xFFFFFFFFu, q1, o);
            }
            if (lane < 4) {
                float* sred = (float*)dsm;   // [wid][nt][lq][2], sq at +256
                const int base = ((wid * 4 + nt) * 4 + lane) * 2;
                sred[base]     = s0;
                sred[base + 1] = s1;
                sred[256 + base]     = q0;
                sred[256 + base + 1] = q1;
            }
        }
    }
    if (EPI == 1) {
        __syncthreads();
        if (tid < 128) {   // one thread per block column
            const float* sred = (const float*)dsm;
            const int g = tid >> 5, rem = tid & 31;
            const int nt = rem >> 3, lq = (rem & 7) >> 1, c = rem & 1;
            const int i0 = ((g * 4 + nt) * 4 + lq) * 2 + c;        // m_base 0 warp
            const int i1 = (((g + 4) * 4 + nt) * 4 + lq) * 2 + c;  // m_base 64 warp
            g_ps[(size_t)blockIdx.y * H_DIM + n0 + rem + g * 32] = sred[i0] + sred[i1];
            g_pq[(size_t)blockIdx.y * H_DIM + n0 + rem + g * 32] = sred[256 + i0] + sred[256 + i1];
        }
    }
}

// ---------------- hi/hj: K-split fp32 GEMM (128 blocks) + reduce ---------------
__launch_bounds__(256)
__global__ void gemm_hij(const float* __restrict__ feats, const float* __restrict__ W1)
{
    const int which = blockIdx.z >> 2;
    const int kc = blockIdx.z & 3;
    __shared__ float As[8][132];
    __shared__ float Bs[8][128];
    const int tid = threadIdx.x;
    const int tx = tid & 15, ty = tid >> 4;
    const int m0 = blockIdx.y * 128, n0 = blockIdx.x * 128;
    float acc[8][8];
#pragma unroll
    for (int i = 0; i < 8; i++)
#pragma unroll
        for (int j = 0; j < 8; j++) acc[i][j] = 0.f;
    const int ar = tid >> 1, ak = (tid & 1) * 4;
    const int bk = tid >> 5, bc = (tid & 31) * 4;
    const float* Aptr = feats + (size_t)(m0 + ar) * 1024 + kc * 256 + ak;
    const float* Bptr = W1 + (size_t)(which * D_IN + kc * 256 + bk) * 1024 + n0 + bc;
    for (int k0 = 0; k0 < 256; k0 += 8) {
        float4 av = *(const float4*)(Aptr + k0);
        float4 bv = *(const float4*)(Bptr + (size_t)k0 * 1024);
        As[ak][ar] = av.x; As[ak + 1][ar] = av.y; As[ak + 2][ar] = av.z; As[ak + 3][ar] = av.w;
        *(float4*)(&Bs[bk][bc]) = bv;
        __syncthreads();
#pragma unroll
        for (int kk = 0; kk < 8; kk++) {
            float a[8], b[8];
#pragma unroll
            for (int i = 0; i < 8; i++) a[i] = As[kk][ty * 8 + i];
#pragma unroll
            for (int j = 0; j < 8; j++) b[j] = Bs[kk][tx * 8 + j];
#pragma unroll
            for (int i = 0; i < 8; i++)
#pragma unroll
                for (int j = 0; j < 8; j++) acc[i][j] += a[i] * b[j];
        }
        __syncthreads();
    }
    float* dst = g_part + (size_t)blockIdx.z * N_OBJ * H_DIM;
#pragma unroll
    for (int i = 0; i < 8; i++)
#pragma unroll
        for (int j = 0; j < 8; j++)
            dst[(size_t)(m0 + ty * 8 + i) * 1024 + n0 + tx * 8 + j] = acc[i][j];
}

__global__ void reduce_hij()
{
    const int idx = blockIdx.x * 256 + threadIdx.x;
    const int which = idx >> 18;
    const int base = idx & (N_OBJ * H_DIM - 1);
    const size_t stride = (size_t)N_OBJ * H_DIM;
    const float* p = g_part + (size_t)which * 4 * stride + base;
    const float s = p[0] + p[stride] + p[2 * stride] + p[3 * stride];
    if (which == 0) g_hi[base] = s;
    else            g_hj[base] = s;
}

// ---------------- converters ---------------------------------------------------
__global__ void convert_cemb(const float* __restrict__ in)   // fp32 -> fp16 single
{
    const size_t i = ((size_t)blockIdx.x * 256 + threadIdx.x) * 4;
    if (i >= (size_t)NP * C_EMB) return;
    const float4 v4 = *(const float4*)(in + i);
    __half2 p0 = __halves2half2(__float2half_rn(v4.x), __float2half_rn(v4.y));
    __half2 p1 = __halves2half2(__float2half_rn(v4.z), __float2half_rn(v4.w));
    *(uint2*)((char*)g_c + i * 2) = make_uint2(*(uint32_t*)&p0, *(uint32_t*)&p1);
}

// W1c^T split via 32x32 tiled transpose. grid (C_EMB/32, H_DIM/32), 256 thr.
__global__ void split_W1t(const float* __restrict__ W1)
{
    __shared__ float t[32][33];
    const int kb = blockIdx.x * 32;
    const int jb = blockIdx.y * 32;
    const int tx = threadIdx.x & 31, ty = threadIdx.x >> 5;
#pragma unroll
    for (int r = 0; r < 4; r++) {
        const int k = kb + ty + r * 8;
        t[ty + r * 8][tx] = W1[(size_t)(2 * D_IN + k) * H_DIM + jb + tx];
    }
    __syncthreads();
#pragma unroll
    for (int r = 0; r < 4; r++) {
        const int j = jb + ty + r * 8;
        const int k = kb + tx;
        __half h, l;
        split_fp16(t[tx][ty + r * 8], h, l);
        g_W1t_hi[(size_t)j * C_EMB + k] = h;
        g_W1t_lo[(size_t)j * C_EMB + k] = l;
    }
}

// wrelc = W2 @ W_rel [1024,51], wattc = W2 @ w_att [1024]  (one block per k-row)
__global__ void small_mats(const float* __restrict__ W2, const float* __restrict__ Wrel,
                           const float* __restrict__ watt)
{
    __shared__ float row[1024];
    const int i = blockIdx.x, tid = threadIdx.x;
    for (int o = tid; o < 1024; o += 256) row[o] = W2[(size_t)i * O_DIM + o];
    __syncthreads();
    if (tid < R_DIM) {
        float s = 0.f;
        for (int o = 0; o < 1024; o++) s += row[o] * Wrel[(size_t)o * R_DIM + tid];
        g_wrelc[i * R_DIM + tid] = s;
    } else if (tid == R_DIM) {
        float s = 0.f;
        for (int o = 0; o < 1024; o++) s += row[o] * watt[o];
        g_wattc[i] = s;
    }
}

// (scale.W2)^T split via 32x32 tiled transpose (cols 0..1023)
__global__ void build_W2ts(const float* __restrict__ W2)
{
    __shared__ float t[32][33];
    const int kb = blockIdx.x * 32;
    const int jb = blockIdx.y * 32;
    const int tx = threadIdx.x & 31, ty = threadIdx.x >> 5;
#pragma unroll
    for (int r = 0; r < 4; r++) {
        const int k = kb + ty + r * 8;
        t[ty + r * 8][tx] = W2[(size_t)k * O_DIM + jb + tx];
    }
    __syncthreads();
#pragma unroll
    for (int r = 0; r < 4; r++) {
        const int j = jb + ty + r * 8;
        const int k = kb + tx;
        __half h, l;
        split_fp16(g_scale[k] * t[tx][ty + r * 8], h, l);
        g_W2t_hi[(size_t)j * H_DIM + k] = h;
        g_W2t_lo[(size_t)j * H_DIM + k] = l;
    }
}

// extra B^T columns 1024..1151: rel (scale.wrelc), conf (scale.wattc), zero pad
__global__ void build_Bextra()
{
    const int j = 1024 + blockIdx.x;
    const int k = blockIdx.y * 256 + threadIdx.x;
    const int j0 = j - 1024;
    float w = 0.f;
    if (j0 < R_DIM)       w = g_scale[k] * g_wrelc[k * R_DIM + j0];
    else if (j0 == R_DIM) w = g_scale[k] * g_wattc[k];
    __half h, l;
    split_fp16(w, h, l);
    g_W2t_hi[(size_t)j * H_DIM + k] = h;
    g_W2t_lo[(size_t)j * H_DIM + k] = l;
}

// bias2[j<1024] = b2[j] + sum_k shift[k] * W2[k][j]
__global__ void build_bias2(const float* __restrict__ W2, const float* __restrict__ b2)
{
    const int j = blockIdx.x * 256 + threadIdx.x;
    float s = b2[j];
#pragma unroll 4
    for (int k = 0; k < H_DIM; k++)
        s += g_shift[k] * W2[(size_t)k * O_DIM + j];
    g_bias2[j] = s;
}

// bias2[1024+j0]: rel -> bias2[:1024]@Wrel + brel ; conf -> bias2.watt + batt ; 0 pad
__global__ void build_biasX(const float* __restrict__ Wrel, const float* __restrict__ brel,
                            const float* __restrict__ watt, const float* __restrict__ batt)
{
    __shared__ float red[256];
    const int j0 = blockIdx.x, tid = threadIdx.x;
    float a = 0.f;
    if (j0 < R_DIM) {
        for (int o = tid; o < 1024; o += 256) a += g_bias2[o] * Wrel[(size_t)o * R_DIM + j0];
    } else if (j0 == R_DIM) {
        for (int o = tid; o < 1024; o += 256) a += g_bias2[o] * watt[o];
    }
    red[tid] = a;
    __syncthreads();
    for (int o = 128; o; o >>= 1) {
        if (tid < o) red[tid] += red[tid + o];
        __syncthreads();
    }
    if (tid == 0) {
        float b = 0.f;
        if (j0 < R_DIM)       b = red[0] + brel[j0];
        else if (j0 == R_DIM) b = red[0] + batt[0];
        g_bias2[1024 + j0] = b;
    }
}

// ---------------- BN finalize from fused per-m-block partials ------------------
__global__ void finalize_bn(const float* __restrict__ gamma, const float* __restrict__ beta)
{
    const int c = blockIdx.x * 256 + threadIdx.x;
    float s = 0.f, q = 0.f;
#pragma unroll 8
    for (int i = 0; i < MBLK; i++) { s += g_ps[i * H_DIM + c]; q += g_pq[i * H_DIM + c]; }
    const float inv = 1.0f / (float)NP;
    const float mean = s * inv;
    const float var = q * inv - mean * mean;
    const float sc = gamma[c] * rsqrtf(var + BN_EPS);
    g_scale[c] = sc;
    g_shift[c] = beta[c] - mean * sc;
}

// ---------------- softmax + weighted aggregation -------------------------------
__global__ void attn_agg(const float* __restrict__ feat, float* __restrict__ enhanced)
{
    __shared__ float conf[N_OBJ];
    __shared__ float red[256];
    const int n = blockIdx.x, tid = threadIdx.x;
    const int c0 = blockIdx.y * 256;
    const float v = g_conf[n * N_OBJ + tid];
    red[tid] = v;
    __syncthreads();
    for (int o = 128; o; o >>= 1) {
        if (tid < o) red[tid] = fmaxf(red[tid], red[tid + o]);
        __syncthreads();
    }
    const float mx = red[0];
    __syncthreads();
    const float e = expf(v - mx);
    red[tid] = e;
    __syncthreads();
    for (int o = 128; o; o >>= 1) {
        if (tid < o) red[tid] += red[tid + o];
        __syncthreads();
    }
    const float p = e / red[0];
    __syncthreads();
    conf[tid] = p;
    __syncthreads();

    float acc = 0.f;
    const float* base = feat + (size_t)n * N_OBJ * O_DIM + c0 + tid;
#pragma unroll 4
    for (int m = 0; m < N_OBJ; m++)
        acc += conf[m] * base[(size_t)m * O_DIM];
    enhanced[(size_t)n * O_DIM + c0 + tid] = acc;
}

// ---------------- launcher ------------------------------------------------------
// NOTE: every kernel argument below is a d_in/d_out pointer. Device scratch is
// reached only through device-code symbol references.
extern "C" void kernel_launch(void* const* d_in, const int* in_sizes, int n_in,
                              void* d_out, int out_size)
{
    const float* feats = (const float*)d_in[0];
    const float* cemb  = (const float*)d_in[1];
    const float* W1    = (const float*)d_in[2];
    const float* b1    = (const float*)d_in[3];
    const float* gamma = (const float*)d_in[4];
    const float* beta  = (const float*)d_in[5];
    const float* W2    = (const float*)d_in[6];
    const float* b2    = (const float*)d_in[7];
    const float* watt  = (const float*)d_in[8];
    const float* batt  = (const float*)d_in[9];
    const float* Wrel  = (const float*)d_in[10];
    const float* brel  = (const float*)d_in[11];

    float* out      = (float*)d_out;
    float* feat     = out;
    float* enhanced = out + (size_t)NP * O_DIM;
    float* relation = enhanced + (size_t)N_OBJ * O_DIM;

    // TK=32 path: 3 planes x 2 stages x 128 x 40 halves = 60KB dynamic smem.
    // Needs opt-in (>48KB default). Fall back to TK=16 (36KB) on failure.
    const int SMEM32 = 3 * 2 * 128 * 40 * 2;   // 61440
    const int SMEM16 = 3 * 2 * 128 * 24 * 2;   // 36864
    cudaError_t ea = cudaFuncSetAttribute(mma_gemm<1, 32>,
        cudaFuncAttributeMaxDynamicSharedMemorySize, SMEM32);
    cudaError_t eb = cudaFuncSetAttribute(mma_gemm<0, 32>,
        cudaFuncAttributeMaxDynamicSharedMemorySize, SMEM32);
    const bool use32 = (ea == cudaSuccess) && (eb == cudaSuccess);

    // converters + small mats (independent of GEMMs)
    convert_cemb<<<(int)(((size_t)NP * C_EMB / 4 + 255) / 256), 256>>>(cemb);
    split_W1t<<<dim3(C_EMB / 32, H_DIM / 32), 256>>>(W1);
    small_mats<<<H_DIM, 256>>>(W2, Wrel, watt);

    // hi/hj: K-split GEMM + deterministic reduce
    gemm_hij<<<dim3(8, 2, 8), 256>>>(feats, W1);
    reduce_hij<<<2 * N_OBJ * H_DIM / 256, 256>>>();

    // GEMM1 (HMMA fp16): h = leakyrelu(...) -> fp16 plane, BN stats fused
    if (use32) mma_gemm<1, 32><<<dim3(8, 512), 256, SMEM32>>>(b1, nullptr, nullptr);
    else       mma_gemm<1, 16><<<dim3(8, 512), 256, SMEM16>>>(b1, nullptr, nullptr);

    // BN finalize + fold into combined B / bias (no separate stats pass)
    finalize_bn<<<4, 256>>>(gamma, beta);
    build_W2ts<<<dim3(H_DIM / 32, O_DIM / 32), 256>>>(W2);
    build_Bextra<<<dim3(128, 4), 256>>>();
    build_bias2<<<O_DIM / 256, 256>>>(W2, b2);
    build_biasX<<<128, 256>>>(Wrel, brel, watt, batt);

    // GEMM2 (HMMA fp16): [feat | relation | conf] = h @ Bcomb + bias2
    if (use32) mma_gemm<0, 32><<<dim3(9, 512), 256, SMEM32>>>(nullptr, feat, relation);
    else       mma_gemm<0, 16><<<dim3(9, 512), 256, SMEM16>>>(nullptr, feat, relation);

    // attention softmax + aggregation (logits from GEMM2)
    attn_agg<<<dim3(N_OBJ, 4), 256>>>(feat, enhanced);
}